// round 14
// baseline (speedup 1.0000x reference)
#include <cuda_runtime.h>
#include <cuda_bf16.h>
#include <math.h>
#include <stdint.h>

#define EMBX 300
#define EMBP 320
#define HX 512
#define HHX 256
#define BX 128
#define LX 128
#define NX (BX*LX)          /* 16384 */
#define SX 10
#define LAYERSX 7
#define K_SAGE 1024

#define SZ_HID (NX*2*HX)
#define OFF_GE SZ_HID
#define OFF_OV (SZ_HID + 2*BX*HX)

// ---------------- scratch (device globals) ----------------
__device__ __align__(16) __nv_bfloat16 g_embh[(size_t)NX*EMBP];
__device__ __align__(16) __nv_bfloat16 g_embl[(size_t)NX*EMBP];
__device__ __align__(16) __nv_bfloat16 g_wihh[2][(size_t)1024*EMBP];
__device__ __align__(16) __nv_bfloat16 g_wihl[2][(size_t)1024*EMBP];
__device__ __align__(16) __nv_bfloat16 g_wh[2][LAYERSX][(size_t)HX*K_SAGE];
__device__ __align__(16) __nv_bfloat16 g_wl[2][LAYERSX][(size_t)HX*K_SAGE];
__device__ __align__(16) __nv_bfloat16 g_cath[2][(size_t)NX*K_SAGE];
__device__ __align__(16) __nv_bfloat16 g_catl[2][(size_t)NX*K_SAGE];
__device__ __align__(16) float g_xp[2][(size_t)NX*1024];
__device__ __align__(16) float g_nrep[(size_t)(NX+1)*HX];
__device__ __align__(16) float g_hid[2][2][(size_t)(NX+1)*HX];
__device__ __align__(16) float g_len[2][NX];
__device__ __align__(16) float g_bias[2][1024];
__device__ __align__(16) float g_sbias[2][LAYERSX*HX];
__device__ __align__(16) float g_whhq[2][HHX*HHX*4];

// ---------------- helpers ----------------
#define SWZ(o) ((o) ^ (((o) >> 3) & 0x70))

__device__ __forceinline__ uint32_t s2u(const void* p) {
    uint32_t a;
    asm("{ .reg .u64 t; cvta.to.shared.u64 t, %1; cvt.u32.u64 %0, t; }"
        : "=r"(a) : "l"(p));
    return a;
}
__device__ __forceinline__ void cpa16(uint32_t d, const void* g) {
    asm volatile("cp.async.cg.shared.global [%0], [%1], 16;" :: "r"(d), "l"(g));
}
__device__ __forceinline__ void ldsm4(uint32_t* r, uint32_t addr) {
    asm volatile("ldmatrix.sync.aligned.m8n8.x4.shared.b16 {%0,%1,%2,%3}, [%4];"
        : "=r"(r[0]), "=r"(r[1]), "=r"(r[2]), "=r"(r[3]) : "r"(addr));
}
__device__ __forceinline__ void mma16816(float* d, const uint32_t* a, const uint32_t* b) {
    asm volatile("mma.sync.aligned.m16n8k16.row.col.f32.bf16.bf16.f32 "
        "{%0,%1,%2,%3}, {%4,%5,%6,%7}, {%8,%9}, {%0,%1,%2,%3};"
        : "+f"(d[0]), "+f"(d[1]), "+f"(d[2]), "+f"(d[3])
        : "r"(a[0]), "r"(a[1]), "r"(a[2]), "r"(a[3]), "r"(b[0]), "r"(b[1]));
}
__device__ __forceinline__ void bsplit(float a, __nv_bfloat16& h, __nv_bfloat16& l) {
    h = __float2bfloat16(a);
    l = __float2bfloat16(a - __bfloat162float(h));
}
__device__ __forceinline__ float fsig(float x) {
    return __fdividef(1.f, 1.f + __expf(-x));
}
__device__ __forceinline__ float ftanh(float x) {
    float e = __expf(-2.f*x);
    return __fdividef(1.f - e, 1.f + e);
}

// ================= merged preprocessing kernel =================
#define NB_SAGEW 28672   /* 2*7*512*1024/256 */
#define NB_WIH   2560    /* 2*1024*320/256   */
#define NB_EMB   20480   /* 16384*320/256    */
#define NB_WHH   512     /* 2*256*256/256    */
#define NB_BIAS  14      /* 3584/256         */
#define NB_PREP  (NB_SAGEW + NB_WIH + NB_EMB + NB_WHH + NB_BIAS)

__global__ void k_prep(
    const int* __restrict__ feat, const float* __restrict__ Wemb,
    const float* __restrict__ Wihf, const float* __restrict__ Wihb,
    const float* __restrict__ Whhf, const float* __restrict__ Whhb,
    const float* __restrict__ bihf, const float* __restrict__ bhhf,
    const float* __restrict__ bihb, const float* __restrict__ bhhb,
    const float* __restrict__ fwW, const float* __restrict__ bwW,
    const float* __restrict__ fwb, const float* __restrict__ bwb)
{
    int b = blockIdx.x, t = threadIdx.x;
    if (b < NB_SAGEW) {
        const int per = LAYERSX*HX*K_SAGE;
        int idx = b*256 + t;
        int d = idx / per, rem = idx - d*per;
        float v = (d ? bwW : fwW)[rem];
        __nv_bfloat16 h, l; bsplit(v, h, l);
        (&g_wh[0][0][0])[(size_t)d*per + rem] = h;
        (&g_wl[0][0][0])[(size_t)d*per + rem] = l;
        return;
    }
    b -= NB_SAGEW;
    if (b < NB_WIH) {
        int idx = b*256 + t;
        int d = idx / (1024*EMBP);
        int rem = idx - d*(1024*EMBP);
        int r = rem / EMBP, e = rem - r*EMBP;
        const float* W = d ? Wihb : Wihf;
        float v = (e < EMBX) ? W[(size_t)r*EMBX + e] : 0.f;
        __nv_bfloat16 h, l; bsplit(v, h, l);
        g_wihh[d][rem] = h; g_wihl[d][rem] = l;
        return;
    }
    b -= NB_WIH;
    if (b < NB_EMB) {
        int idx = b*256 + t;
        int n = idx / EMBP, e = idx - n*EMBP;
        float v = 0.f;
        if (e < EMBX) v = Wemb[(size_t)feat[n]*EMBX + e];
        __nv_bfloat16 h, l; bsplit(v, h, l);
        g_embh[idx] = h; g_embl[idx] = l;
        return;
    }
    b -= NB_EMB;
    if (b < NB_WHH) {
        int idx = b*256 + t;
        int d = idx / (HHX*HHX);
        int rem = idx - d*(HHX*HHX);
        int k = rem / HHX, j = rem - k*HHX;
        const float* W = d ? Whhb : Whhf;
        float4 v;
        v.x = W[(size_t)(0*HHX + j)*HHX + k];
        v.y = W[(size_t)(1*HHX + j)*HHX + k];
        v.z = W[(size_t)(2*HHX + j)*HHX + k];
        v.w = W[(size_t)(3*HHX + j)*HHX + k];
        *(float4*)&g_whhq[d][(size_t)rem*4] = v;
        return;
    }
    b -= NB_WHH;
    {
        int j = b*256 + t;
        if (j < 4*HHX) {
            g_bias[0][j] = bihf[j] + bhhf[j];
            g_bias[1][j] = bihb[j] + bhhb[j];
        }
        if (j < LAYERSX*HX) {
            g_sbias[0][j] = fwb[j];
            g_sbias[1][j] = bwb[j];
        }
    }
}

// ============ mma.sync bf16x3 GEMM, dual-direction via blockIdx.z ==========
__device__ __forceinline__ void load_stage(
    uint32_t sb, int s, int kc,
    const char* A0, const char* A1, const char* B0, const char* B1,
    int K, int tid)
{
    const char* srcs[4] = { A0, A1, B0, B1 };
    uint32_t stb = sb + s*65536;
#pragma unroll
    for (int t4 = 0; t4 < 4; t4++) {
        const char* src = srcs[t4] + (size_t)kc*128;
        uint32_t tb = stb + t4*16384;
#pragma unroll
        for (int i = 0; i < 4; i++) {
            int q = tid + i*256;
            int r = q >> 3, sc = q & 7;
            cpa16(tb + SWZ(r*128 + sc*16), src + (size_t)r*(size_t)K*2 + sc*16);
        }
    }
    asm volatile("cp.async.commit_group;" ::: "memory");
}

__global__ __launch_bounds__(256, 1) void k_mma_gemm(
    const __nv_bfloat16* __restrict__ Ah, const __nv_bfloat16* __restrict__ Al,
    const __nv_bfloat16* __restrict__ Bh, const __nv_bfloat16* __restrict__ Bl,
    const float* __restrict__ bias, float* __restrict__ C,
    int Ncols, int K, int relu,
    size_t sA, size_t sB, size_t sBias, size_t sC)
{
    extern __shared__ char dsm[];
    const int z = blockIdx.z;
    Ah += (size_t)z*sA;  Al += (size_t)z*sA;
    Bh += (size_t)z*sB;  Bl += (size_t)z*sB;
    bias += (size_t)z*sBias;
    C  += (size_t)z*sC;

    const int tid = threadIdx.x;
    const int wid = tid >> 5, lane = tid & 31;
    const int row0 = blockIdx.y << 7;
    const int col0 = blockIdx.x << 7;
    const int nch = K >> 6;

    uint32_t sb = s2u(dsm);
    sb = (sb + 1023u) & ~1023u;

    const char* A0 = (const char*)(Ah + (size_t)row0*K);
    const char* A1 = (const char*)(Al + (size_t)row0*K);
    const char* B0 = (const char*)(Bh + (size_t)col0*K);
    const char* B1 = (const char*)(Bl + (size_t)col0*K);

    const int wm = (wid >> 1) * 32;
    const int wn = (wid & 1) * 64;
    const int gq8 = lane >> 3, lr = lane & 7;
    const int a_row = wm + lr + ((gq8 & 1) << 3);
    const int a_cb  = (gq8 >> 1) << 4;
    const int b_row = wn + lr + ((gq8 >> 1) << 3);
    const int b_cb  = (gq8 & 1) << 4;

    float acc[2][8][4];
#pragma unroll
    for (int mt = 0; mt < 2; mt++)
#pragma unroll
        for (int nt = 0; nt < 8; nt++)
#pragma unroll
            for (int j = 0; j < 4; j++) acc[mt][nt][j] = 0.f;

    load_stage(sb, 0, 0, A0, A1, B0, B1, K, tid);
    if (nch > 1) load_stage(sb, 1, 1, A0, A1, B0, B1, K, tid);

    int sidx = 0;
    for (int kc = 0; kc < nch; kc++) {
        if (kc + 1 < nch)
            asm volatile("cp.async.wait_group 1;" ::: "memory");
        else
            asm volatile("cp.async.wait_group 0;" ::: "memory");
        __syncthreads();
        if (kc + 2 < nch) {
            int ls = sidx + 2; if (ls >= 3) ls -= 3;
            load_stage(sb, ls, kc + 2, A0, A1, B0, B1, K, tid);
        }
        const uint32_t stb = sb + sidx*65536;
#pragma unroll
        for (int ks = 0; ks < 4; ks++) {
            const int k0b = ks * 32;
            uint32_t ah[2][4], al[2][4];
#pragma unroll
            for (int mt = 0; mt < 2; mt++) {
                uint32_t off = SWZ((uint32_t)((a_row + mt*16)*128 + (a_cb + k0b)));
                ldsm4(ah[mt], stb + off);
                ldsm4(al[mt], stb + 16384 + off);
            }
            uint32_t bh[4][4], bl[4][4];
#pragma unroll
            for (int gg = 0; gg < 4; gg++) {
                uint32_t off = SWZ((uint32_t)((b_row + gg*16)*128 + (b_cb + k0b)));
                ldsm4(bh[gg], stb + 32768 + off);
                ldsm4(bl[gg], stb + 49152 + off);
            }
#pragma unroll
            for (int mt = 0; mt < 2; mt++)
#pragma unroll
                for (int nt = 0; nt < 8; nt++) {
                    const uint32_t* bhp = &bh[nt >> 1][(nt & 1) * 2];
                    const uint32_t* blp = &bl[nt >> 1][(nt & 1) * 2];
                    mma16816(acc[mt][nt], ah[mt], bhp);
                    mma16816(acc[mt][nt], ah[mt], blp);
                    mma16816(acc[mt][nt], al[mt], bhp);
                }
        }
        sidx++; if (sidx >= 3) sidx = 0;
    }

    const int erow = row0 + wm + (lane >> 2);
    const int ecol = col0 + wn + 2*(lane & 3);
#pragma unroll
    for (int mt = 0; mt < 2; mt++)
#pragma unroll
        for (int nt = 0; nt < 8; nt++) {
            int r = erow + mt*16;
            int cc = ecol + nt*8;
            float2 v0, v1;
            v0.x = acc[mt][nt][0] + bias[cc];
            v0.y = acc[mt][nt][1] + bias[cc+1];
            v1.x = acc[mt][nt][2] + bias[cc];
            v1.y = acc[mt][nt][3] + bias[cc+1];
            if (relu) {
                v0.x = fmaxf(v0.x, 0.f); v0.y = fmaxf(v0.y, 0.f);
                v1.x = fmaxf(v1.x, 0.f); v1.y = fmaxf(v1.y, 0.f);
            }
            *(float2*)&C[(size_t)r*Ncols + cc]     = v0;
            *(float2*)&C[(size_t)(r+8)*Ncols + cc] = v1;
        }
}

// ---------------- persistent BiLSTM (R9: scalar FFMA, fast gates) ----------
__global__ __launch_bounds__(256) void k_lstm()
{
    const int dir = blockIdx.x >> 5;
    const int rg  = blockIdx.x & 31;
    const int j = threadIdx.x;
    const float* __restrict__ Wq = g_whhq[dir];
    const float* __restrict__ xp = g_xp[dir];
    __shared__ float hbuf[2][4][HHX];
#pragma unroll
    for (int r = 0; r < 4; r++) hbuf[0][r][j] = 0.f;
    float c[4] = {0.f, 0.f, 0.f, 0.f};
    __syncthreads();
    int p = 0;
    for (int t = 0; t < LX; t++) {
        const int tseq = dir ? (LX - 1 - t) : t;
        float a0[4] = {0,0,0,0}, a1[4] = {0,0,0,0};
        float a2[4] = {0,0,0,0}, a3[4] = {0,0,0,0};
#pragma unroll 4
        for (int k = 0; k < HHX; k++) {
            float4 w = *(const float4*)&Wq[((size_t)k*HHX + j)*4];
#pragma unroll
            for (int r = 0; r < 4; r++) {
                float hv = hbuf[p][r][k];
                a0[r] = fmaf(w.x, hv, a0[r]);
                a1[r] = fmaf(w.y, hv, a1[r]);
                a2[r] = fmaf(w.z, hv, a2[r]);
                a3[r] = fmaf(w.w, hv, a3[r]);
            }
        }
#pragma unroll
        for (int r = 0; r < 4; r++) {
            const int row = rg*4 + r;
            const size_t nidx = (size_t)row*LX + tseq;
            const float* xr = xp + nidx*(4*HHX);
            float gi = a0[r] + xr[j];
            float gf = a1[r] + xr[HHX + j];
            float gg = a2[r] + xr[2*HHX + j];
            float go = a3[r] + xr[3*HHX + j];
            float si = fsig(gi), sf = fsig(gf), so = fsig(go);
            float tg = ftanh(gg);
            c[r] = sf*c[r] + si*tg;
            float hv = so * ftanh(c[r]);
            hbuf[p ^ 1][r][j] = hv;
            g_nrep[nidx*HX + (size_t)dir*HHX + j] = hv;
        }
        __syncthreads();
        p ^= 1;
    }
}

// ------ merged init: pad nrep row N, zero hid rows N, hid = nrep[nodes] ----
__global__ void k_init(const int* __restrict__ nodes, const float* __restrict__ pad)
{
    int idx = blockIdx.x * blockDim.x + threadIdx.x;
    if (idx < HX) {
        g_nrep[(size_t)NX*HX + idx] = pad[idx];
        g_hid[0][0][(size_t)NX*HX + idx] = 0.f;
        g_hid[0][1][(size_t)NX*HX + idx] = 0.f;
        g_hid[1][0][(size_t)NX*HX + idx] = 0.f;
        g_hid[1][1][(size_t)NX*HX + idx] = 0.f;
    }
    if (idx >= NX*HX) return;
    int n = idx >> 9, cc = idx & (HX - 1);
    float v = g_nrep[(size_t)nodes[n]*HX + cc];
    g_hid[0][0][idx] = v;
    g_hid[1][0][idx] = v;
}

// ------- gather + mean + concat -> bf16 hi/lo cat; optional len compute ----
__global__ __launch_bounds__(128) void k_gm(
    const float* __restrict__ selfT, size_t sSelf,
    const float* __restrict__ neighT, size_t sNeigh,
    const int* __restrict__ nodes,
    const int* __restrict__ adjF, const int* __restrict__ adjB,
    int computeLen)
{
    const int n = blockIdx.x;
    const int dir = blockIdx.y;
    selfT  += (size_t)dir*sSelf;
    neighT += (size_t)dir*sNeigh;
    const int* adj = dir ? adjB : adjF;
    __nv_bfloat16* cath = g_cath[dir];
    __nv_bfloat16* catl = g_catl[dir];

    const int t = threadIdx.x;
    __shared__ int nb[SX];
    __shared__ float s_red[4][SX];
    __shared__ float s_inv;
    if (t < SX) nb[t] = adj[(size_t)nodes[n]*SX + t];
    if (!computeLen && t == 0) s_inv = 1.f / g_len[dir][n];
    __syncthreads();

    const int c = t * 4;
    float4 s = {0.f, 0.f, 0.f, 0.f};
    float rq[SX];
#pragma unroll
    for (int q = 0; q < SX; q++) {
        const float4 v = *(const float4*)&neighT[(size_t)nb[q]*HX + c];
        s.x += v.x; s.y += v.y; s.z += v.z; s.w += v.w;
        if (computeLen) {
            rq[q] = fmaxf(v.x, 0.f) + fmaxf(v.y, 0.f)
                  + fmaxf(v.z, 0.f) + fmaxf(v.w, 0.f);
        }
    }
    if (computeLen) {
        const int lane = t & 31, w = t >> 5;
#pragma unroll
        for (int q = 0; q < SX; q++) {
            float x = rq[q];
#pragma unroll
            for (int o = 16; o; o >>= 1) x += __shfl_xor_sync(0xffffffffu, x, o);
            if (lane == 0) s_red[w][q] = x;
        }
        __syncthreads();
        if (t == 0) {
            float cnt = 0.f;
#pragma unroll
            for (int q = 0; q < SX; q++) {
                float tot = s_red[0][q] + s_red[1][q] + s_red[2][q] + s_red[3][q];
                if (tot > 0.f) cnt += 1.f;
            }
            g_len[dir][n] = cnt;
            s_inv = 1.f / cnt;
        }
        __syncthreads();
    }
    const float invlen = s_inv;

    float4 sv = *(const float4*)&selfT[(size_t)n*HX + c];
    float4 m = {s.x*invlen, s.y*invlen, s.z*invlen, s.w*invlen};

    size_t o = (size_t)n*K_SAGE + c;
    __nv_bfloat16 h0,l0,h1,l1,h2,l2,h3,l3;
    bsplit(sv.x,h0,l0); bsplit(sv.y,h1,l1); bsplit(sv.z,h2,l2); bsplit(sv.w,h3,l3);
    *(__nv_bfloat162*)&cath[o]   = __halves2bfloat162(h0,h1);
    *(__nv_bfloat162*)&cath[o+2] = __halves2bfloat162(h2,h3);
    *(__nv_bfloat162*)&catl[o]   = __halves2bfloat162(l0,l1);
    *(__nv_bfloat162*)&catl[o+2] = __halves2bfloat162(l2,l3);

    bsplit(m.x,h0,l0); bsplit(m.y,h1,l1); bsplit(m.z,h2,l2); bsplit(m.w,h3,l3);
    *(__nv_bfloat162*)&cath[o+HX]   = __halves2bfloat162(h0,h1);
    *(__nv_bfloat162*)&cath[o+HX+2] = __halves2bfloat162(h2,h3);
    *(__nv_bfloat162*)&catl[o+HX]   = __halves2bfloat162(l0,l1);
    *(__nv_bfloat162*)&catl[o+HX+2] = __halves2bfloat162(l2,l3);
}

// ---------------- fused finalize + maxpool ----------------
__global__ __launch_bounds__(1024) void k_finpool(float* __restrict__ out, int fin)
{
    const int b = blockIdx.x;
    const int t = threadIdx.x;        // 0..1023
    const int dirv = t >> 9, cc = t & 511;
    const float* hsrc = g_hid[dirv][fin];
    float m = -3.402823466e38f;
    for (int l = 0; l < LX; l++) {
        const int n = b*LX + l;
        float v = hsrc[(size_t)n*HX + cc];
        out[(size_t)n*1024 + t] = v;
        m = fmaxf(m, v);
        if (t < 512)
            out[(size_t)OFF_OV + (size_t)n*HX + t] = g_nrep[(size_t)n*HX + t];
    }
    out[(size_t)OFF_GE + (size_t)b*1024 + t] = m;
}

// ============================ host launcher ================================
extern "C" void kernel_launch(void* const* d_in, const int* in_sizes, int n_in,
                              void* d_out, int out_size)
{
    const int*   feature_info = (const int*)d_in[0];
    const int*   batch_nodes  = (const int*)d_in[1];
    const int*   fw_adj       = (const int*)d_in[2];
    const int*   bw_adj       = (const int*)d_in[3];
    const float* W_emb        = (const float*)d_in[4];
    const float* Wih_f        = (const float*)d_in[5];
    const float* Whh_f        = (const float*)d_in[6];
    const float* bih_f        = (const float*)d_in[7];
    const float* bhh_f        = (const float*)d_in[8];
    const float* Wih_b        = (const float*)d_in[9];
    const float* Whh_b        = (const float*)d_in[10];
    const float* bih_b        = (const float*)d_in[11];
    const float* bhh_b        = (const float*)d_in[12];
    const float* padding_vec  = (const float*)d_in[13];
    const float* fw_W         = (const float*)d_in[14];
    const float* fw_b         = (const float*)d_in[15];
    const float* bw_W         = (const float*)d_in[16];
    const float* bw_b         = (const float*)d_in[17];
    float* out = (float*)d_out;

    const int DSMEM = 3*65536 + 1024;
    cudaFuncSetAttribute(k_mma_gemm, cudaFuncAttributeMaxDynamicSharedMemorySize, DSMEM);

    float *p_nrep, *p_hid, *p_bias, *p_sbias, *p_xp;
    __nv_bfloat16 *p_embh, *p_embl, *p_wihh, *p_wihl, *p_wh, *p_wl, *p_cath, *p_catl;
    cudaGetSymbolAddress((void**)&p_nrep, g_nrep);
    cudaGetSymbolAddress((void**)&p_hid,  g_hid);
    cudaGetSymbolAddress((void**)&p_bias, g_bias);
    cudaGetSymbolAddress((void**)&p_sbias,g_sbias);
    cudaGetSymbolAddress((void**)&p_xp,   g_xp);
    cudaGetSymbolAddress((void**)&p_embh, g_embh);
    cudaGetSymbolAddress((void**)&p_embl, g_embl);
    cudaGetSymbolAddress((void**)&p_wihh, g_wihh);
    cudaGetSymbolAddress((void**)&p_wihl, g_wihl);
    cudaGetSymbolAddress((void**)&p_wh,   g_wh);
    cudaGetSymbolAddress((void**)&p_wl,   g_wl);
    cudaGetSymbolAddress((void**)&p_cath, g_cath);
    cudaGetSymbolAddress((void**)&p_catl, g_catl);

    const size_t HIDQ = (size_t)(NX+1)*HX;
    const size_t HIDD = 2*HIDQ;
    float* hid_d[2][2];
    for (int d = 0; d < 2; d++)
        for (int q = 0; q < 2; q++)
            hid_d[d][q] = p_hid + ((size_t)d*2 + q)*HIDQ;

    // 1. merged preprocessing
    k_prep<<<NB_PREP, 256>>>(feature_info, W_emb, Wih_f, Wih_b, Whh_f, Whh_b,
                             bih_f, bhh_f, bih_b, bhh_b, fw_W, bw_W, fw_b, bw_b);

    // 2. input projections, both dirs in one launch (bf16x3 mma)
    dim3 gxp(1024/128, NX/128, 2);
    k_mma_gemm<<<gxp, 256, DSMEM>>>(p_embh, p_embl, p_wihh, p_wihl,
                                    p_bias, p_xp, 1024, EMBP, 0,
                                    0, (size_t)1024*EMBP, 1024, (size_t)NX*1024);

    // 3. persistent BiLSTM -> g_nrep rows 0..N-1
    k_lstm<<<64, 256>>>();

    // 4. merged init (pad row, zero rows, initial hidden)
    k_init<<<(NX*HX + 255)/256, 256>>>(batch_nodes, padding_vec);

    // 5. 7 SAGE layers, both dirs per launch; layer 0 fuses len computation
    int pin = 0;
    dim3 ggm(NX, 2);
    dim3 gsage(HX/128, NX/128, 2);
    for (int l = 0; l < LAYERSX; l++) {
        if (l == 0)
            k_gm<<<ggm, 128>>>(hid_d[0][pin], HIDD, p_nrep, 0,
                               batch_nodes, fw_adj, bw_adj, 1);
        else
            k_gm<<<ggm, 128>>>(hid_d[0][pin], HIDD, hid_d[0][pin], HIDD,
                               batch_nodes, fw_adj, bw_adj, 0);
        k_mma_gemm<<<gsage, 256, DSMEM>>>(
            p_cath, p_catl,
            p_wh + (size_t)l*HX*K_SAGE, p_wl + (size_t)l*HX*K_SAGE,
            p_sbias + (size_t)l*HX, hid_d[0][1 - pin],
            HX, K_SAGE, 1,
            (size_t)NX*K_SAGE, (size_t)LAYERSX*HX*K_SAGE,
            (size_t)LAYERSX*HX, HIDD);
        pin ^= 1;
    }

    // 6. fused finalize + pool (final hidden in buffer index pin = 1)
    k_finpool<<<BX, 1024>>>(out, pin);
    (void)in_sizes; (void)n_in; (void)out_size;
}

// round 15
// speedup vs baseline: 1.0226x; 1.0226x over previous
#include <cuda_runtime.h>
#include <cuda_bf16.h>
#include <math.h>
#include <stdint.h>

#define EMBX 300
#define EMBP 320
#define HX 512
#define HHX 256
#define BX 128
#define LX 128
#define NX (BX*LX)          /* 16384 */
#define SX 10
#define LAYERSX 7
#define K_SAGE 1024

#define SZ_HID (NX*2*HX)
#define OFF_GE SZ_HID
#define OFF_OV (SZ_HID + 2*BX*HX)

// ---------------- scratch (device globals) ----------------
__device__ __align__(16) __nv_bfloat16 g_embh[(size_t)NX*EMBP];
__device__ __align__(16) __nv_bfloat16 g_embl[(size_t)NX*EMBP];
__device__ __align__(16) __nv_bfloat16 g_wihh[2][(size_t)1024*EMBP];
__device__ __align__(16) __nv_bfloat16 g_wihl[2][(size_t)1024*EMBP];
__device__ __align__(16) __nv_bfloat16 g_wh[2][LAYERSX][(size_t)HX*K_SAGE];
__device__ __align__(16) __nv_bfloat16 g_wl[2][LAYERSX][(size_t)HX*K_SAGE];
__device__ __align__(16) __nv_bfloat16 g_cath[2][(size_t)NX*K_SAGE];
__device__ __align__(16) __nv_bfloat16 g_catl[2][(size_t)NX*K_SAGE];
__device__ __align__(16) float g_xp[2][(size_t)NX*1024];
__device__ __align__(16) float g_nrep[(size_t)(NX+1)*HX];
__device__ __align__(16) float g_hid[2][2][(size_t)(NX+1)*HX];
__device__ __align__(16) float g_len[2][NX];
__device__ __align__(16) float g_bias[2][1024];
__device__ __align__(16) float g_sbias[2][LAYERSX*HX];
__device__ __align__(16) float g_whhq[2][HHX*HHX*4];

// ---------------- helpers ----------------
#define SWZ(o) ((o) ^ (((o) >> 3) & 0x70))

__device__ __forceinline__ uint32_t s2u(const void* p) {
    uint32_t a;
    asm("{ .reg .u64 t; cvta.to.shared.u64 t, %1; cvt.u32.u64 %0, t; }"
        : "=r"(a) : "l"(p));
    return a;
}
__device__ __forceinline__ void cpa16(uint32_t d, const void* g) {
    asm volatile("cp.async.cg.shared.global [%0], [%1], 16;" :: "r"(d), "l"(g));
}
__device__ __forceinline__ void ldsm4(uint32_t* r, uint32_t addr) {
    asm volatile("ldmatrix.sync.aligned.m8n8.x4.shared.b16 {%0,%1,%2,%3}, [%4];"
        : "=r"(r[0]), "=r"(r[1]), "=r"(r[2]), "=r"(r[3]) : "r"(addr));
}
__device__ __forceinline__ void mma16816(float* d, const uint32_t* a, const uint32_t* b) {
    asm volatile("mma.sync.aligned.m16n8k16.row.col.f32.bf16.bf16.f32 "
        "{%0,%1,%2,%3}, {%4,%5,%6,%7}, {%8,%9}, {%0,%1,%2,%3};"
        : "+f"(d[0]), "+f"(d[1]), "+f"(d[2]), "+f"(d[3])
        : "r"(a[0]), "r"(a[1]), "r"(a[2]), "r"(a[3]), "r"(b[0]), "r"(b[1]));
}
__device__ __forceinline__ void bsplit(float a, __nv_bfloat16& h, __nv_bfloat16& l) {
    h = __float2bfloat16(a);
    l = __float2bfloat16(a - __bfloat162float(h));
}
__device__ __forceinline__ float fsig(float x) {
    return __fdividef(1.f, 1.f + __expf(-x));
}
__device__ __forceinline__ float ftanh(float x) {
    float e = __expf(-2.f*x);
    return __fdividef(1.f - e, 1.f + e);
}

// ---------------- embedding lookup -> bf16 hi/lo, K padded to 320 ----------
__global__ void k_embed(const int* __restrict__ feat, const float* __restrict__ Wemb)
{
    int idx = blockIdx.x * blockDim.x + threadIdx.x;
    if (idx >= NX*EMBP) return;
    int n = idx / EMBP, e = idx - n*EMBP;
    float v = 0.f;
    if (e < EMBX) v = Wemb[(size_t)feat[n]*EMBX + e];
    __nv_bfloat16 h, l; bsplit(v, h, l);
    g_embh[idx] = h; g_embl[idx] = l;
}

// ---------------- bias precompute: bih+bhh, packed SAGE biases -------------
__global__ void k_bias(const float* bihf, const float* bhhf,
                       const float* bihb, const float* bhhb,
                       const float* fwb, const float* bwb)
{
    int j = blockIdx.x * blockDim.x + threadIdx.x;
    if (j < 4*HHX) {
        g_bias[0][j] = bihf[j] + bhhf[j];
        g_bias[1][j] = bihb[j] + bhhb[j];
    }
    if (j < LAYERSX*HX) {
        g_sbias[0][j] = fwb[j];
        g_sbias[1][j] = bwb[j];
    }
}

// ---------------- Wih split -> bf16 hi/lo, padded to 320 -------------------
__global__ void k_split_wih(const float* __restrict__ Wf, const float* __restrict__ Wb)
{
    int idx = blockIdx.x * blockDim.x + threadIdx.x;
    if (idx >= 2*1024*EMBP) return;
    int d = idx / (1024*EMBP);
    int rem = idx - d*(1024*EMBP);
    int r = rem / EMBP, e = rem - r*EMBP;
    const float* W = d ? Wb : Wf;
    float v = (e < EMBX) ? W[(size_t)r*EMBX + e] : 0.f;
    __nv_bfloat16 h, l; bsplit(v, h, l);
    g_wihh[d][rem] = h; g_wihl[d][rem] = l;
}

// ---------------- Whh transpose into [k][j][{i,f,g,o}] float4 layout --------
__global__ void k_whhq(const float* __restrict__ Wf, const float* __restrict__ Wb)
{
    int idx = blockIdx.x * blockDim.x + threadIdx.x;
    if (idx >= 2*HHX*HHX) return;
    int d = idx / (HHX*HHX);
    int rem = idx - d*(HHX*HHX);
    int k = rem / HHX, j = rem - k*HHX;
    const float* W = d ? Wb : Wf;
    float4 v;
    v.x = W[(size_t)(0*HHX + j)*HHX + k];
    v.y = W[(size_t)(1*HHX + j)*HHX + k];
    v.z = W[(size_t)(2*HHX + j)*HHX + k];
    v.w = W[(size_t)(3*HHX + j)*HHX + k];
    *(float4*)&g_whhq[d][(size_t)rem*4] = v;
}

// ============ mma.sync bf16x3 GEMM, dual-direction via blockIdx.z ==========
__device__ __forceinline__ void load_stage(
    uint32_t sb, int s, int kc,
    const char* A0, const char* A1, const char* B0, const char* B1,
    int K, int tid)
{
    const char* srcs[4] = { A0, A1, B0, B1 };
    uint32_t stb = sb + s*65536;
#pragma unroll
    for (int t4 = 0; t4 < 4; t4++) {
        const char* src = srcs[t4] + (size_t)kc*128;
        uint32_t tb = stb + t4*16384;
#pragma unroll
        for (int i = 0; i < 4; i++) {
            int q = tid + i*256;
            int r = q >> 3, sc = q & 7;
            cpa16(tb + SWZ(r*128 + sc*16), src + (size_t)r*(size_t)K*2 + sc*16);
        }
    }
    asm volatile("cp.async.commit_group;" ::: "memory");
}

__global__ __launch_bounds__(256, 1) void k_mma_gemm(
    const __nv_bfloat16* __restrict__ Ah, const __nv_bfloat16* __restrict__ Al,
    const __nv_bfloat16* __restrict__ Bh, const __nv_bfloat16* __restrict__ Bl,
    const float* __restrict__ bias, float* __restrict__ C,
    int Ncols, int K, int relu,
    size_t sA, size_t sB, size_t sBias, size_t sC)
{
    extern __shared__ char dsm[];
    const int z = blockIdx.z;
    Ah += (size_t)z*sA;  Al += (size_t)z*sA;
    Bh += (size_t)z*sB;  Bl += (size_t)z*sB;
    bias += (size_t)z*sBias;
    C  += (size_t)z*sC;

    const int tid = threadIdx.x;
    const int wid = tid >> 5, lane = tid & 31;
    const int row0 = blockIdx.y << 7;
    const int col0 = blockIdx.x << 7;
    const int nch = K >> 6;

    uint32_t sb = s2u(dsm);
    sb = (sb + 1023u) & ~1023u;

    const char* A0 = (const char*)(Ah + (size_t)row0*K);
    const char* A1 = (const char*)(Al + (size_t)row0*K);
    const char* B0 = (const char*)(Bh + (size_t)col0*K);
    const char* B1 = (const char*)(Bl + (size_t)col0*K);

    const int wm = (wid >> 1) * 32;
    const int wn = (wid & 1) * 64;
    const int gq8 = lane >> 3, lr = lane & 7;
    const int a_row = wm + lr + ((gq8 & 1) << 3);
    const int a_cb  = (gq8 >> 1) << 4;
    const int b_row = wn + lr + ((gq8 >> 1) << 3);
    const int b_cb  = (gq8 & 1) << 4;

    float acc[2][8][4];
#pragma unroll
    for (int mt = 0; mt < 2; mt++)
#pragma unroll
        for (int nt = 0; nt < 8; nt++)
#pragma unroll
            for (int j = 0; j < 4; j++) acc[mt][nt][j] = 0.f;

    load_stage(sb, 0, 0, A0, A1, B0, B1, K, tid);
    if (nch > 1) load_stage(sb, 1, 1, A0, A1, B0, B1, K, tid);

    int sidx = 0;
    for (int kc = 0; kc < nch; kc++) {
        if (kc + 1 < nch)
            asm volatile("cp.async.wait_group 1;" ::: "memory");
        else
            asm volatile("cp.async.wait_group 0;" ::: "memory");
        __syncthreads();
        if (kc + 2 < nch) {
            int ls = sidx + 2; if (ls >= 3) ls -= 3;
            load_stage(sb, ls, kc + 2, A0, A1, B0, B1, K, tid);
        }
        const uint32_t stb = sb + sidx*65536;
#pragma unroll
        for (int ks = 0; ks < 4; ks++) {
            const int k0b = ks * 32;
            uint32_t ah[2][4], al[2][4];
#pragma unroll
            for (int mt = 0; mt < 2; mt++) {
                uint32_t off = SWZ((uint32_t)((a_row + mt*16)*128 + (a_cb + k0b)));
                ldsm4(ah[mt], stb + off);
                ldsm4(al[mt], stb + 16384 + off);
            }
            uint32_t bh[4][4], bl[4][4];
#pragma unroll
            for (int gg = 0; gg < 4; gg++) {
                uint32_t off = SWZ((uint32_t)((b_row + gg*16)*128 + (b_cb + k0b)));
                ldsm4(bh[gg], stb + 32768 + off);
                ldsm4(bl[gg], stb + 49152 + off);
            }
#pragma unroll
            for (int mt = 0; mt < 2; mt++)
#pragma unroll
                for (int nt = 0; nt < 8; nt++) {
                    const uint32_t* bhp = &bh[nt >> 1][(nt & 1) * 2];
                    const uint32_t* blp = &bl[nt >> 1][(nt & 1) * 2];
                    mma16816(acc[mt][nt], ah[mt], bhp);
                    mma16816(acc[mt][nt], ah[mt], blp);
                    mma16816(acc[mt][nt], al[mt], bhp);
                }
        }
        sidx++; if (sidx >= 3) sidx = 0;
    }

    const int erow = row0 + wm + (lane >> 2);
    const int ecol = col0 + wn + 2*(lane & 3);
#pragma unroll
    for (int mt = 0; mt < 2; mt++)
#pragma unroll
        for (int nt = 0; nt < 8; nt++) {
            int r = erow + mt*16;
            int cc = ecol + nt*8;
            float2 v0, v1;
            v0.x = acc[mt][nt][0] + bias[cc];
            v0.y = acc[mt][nt][1] + bias[cc+1];
            v1.x = acc[mt][nt][2] + bias[cc];
            v1.y = acc[mt][nt][3] + bias[cc+1];
            if (relu) {
                v0.x = fmaxf(v0.x, 0.f); v0.y = fmaxf(v0.y, 0.f);
                v1.x = fmaxf(v1.x, 0.f); v1.y = fmaxf(v1.y, 0.f);
            }
            *(float2*)&C[(size_t)r*Ncols + cc]     = v0;
            *(float2*)&C[(size_t)(r+8)*Ncols + cc] = v1;
        }
}

// ---- persistent BiLSTM (blocks 0-63) + SAGE weight split (blocks 64+) -----
// Wave-1 places bids 0-147 on distinct SMs, so the 64 LSTM blocks own their
// SMs; the 28672 split blocks stream through the remaining ~84 SMs under the
// LSTM's shadow. Split branch has no syncthreads; exits early.
#define NB_SAGEW 28672   /* 2*7*512*1024 / 256 */

__global__ __launch_bounds__(256) void k_lstm(
    const float* __restrict__ fwW, const float* __restrict__ bwW)
{
    if (blockIdx.x >= 64) {
        const int per = LAYERSX*HX*K_SAGE;
        int idx = (blockIdx.x - 64)*256 + threadIdx.x;
        int d = idx / per, rem = idx - d*per;
        float v = (d ? bwW : fwW)[rem];
        __nv_bfloat16 h, l; bsplit(v, h, l);
        (&g_wh[0][0][0])[(size_t)d*per + rem] = h;
        (&g_wl[0][0][0])[(size_t)d*per + rem] = l;
        return;
    }
    const int dir = blockIdx.x >> 5;
    const int rg  = blockIdx.x & 31;
    const int j = threadIdx.x;
    const float* __restrict__ Wq = g_whhq[dir];
    const float* __restrict__ xp = g_xp[dir];
    __shared__ float hbuf[2][4][HHX];
#pragma unroll
    for (int r = 0; r < 4; r++) hbuf[0][r][j] = 0.f;
    float c[4] = {0.f, 0.f, 0.f, 0.f};
    __syncthreads();
    int p = 0;
    for (int t = 0; t < LX; t++) {
        const int tseq = dir ? (LX - 1 - t) : t;
        float a0[4] = {0,0,0,0}, a1[4] = {0,0,0,0};
        float a2[4] = {0,0,0,0}, a3[4] = {0,0,0,0};
#pragma unroll 4
        for (int k = 0; k < HHX; k++) {
            float4 w = *(const float4*)&Wq[((size_t)k*HHX + j)*4];
#pragma unroll
            for (int r = 0; r < 4; r++) {
                float hv = hbuf[p][r][k];
                a0[r] = fmaf(w.x, hv, a0[r]);
                a1[r] = fmaf(w.y, hv, a1[r]);
                a2[r] = fmaf(w.z, hv, a2[r]);
                a3[r] = fmaf(w.w, hv, a3[r]);
            }
        }
#pragma unroll
        for (int r = 0; r < 4; r++) {
            const int row = rg*4 + r;
            const size_t nidx = (size_t)row*LX + tseq;
            const float* xr = xp + nidx*(4*HHX);
            float gi = a0[r] + xr[j];
            float gf = a1[r] + xr[HHX + j];
            float gg = a2[r] + xr[2*HHX + j];
            float go = a3[r] + xr[3*HHX + j];
            float si = fsig(gi), sf = fsig(gf), so = fsig(go);
            float tg = ftanh(gg);
            c[r] = sf*c[r] + si*tg;
            float hv = so * ftanh(c[r]);
            hbuf[p ^ 1][r][j] = hv;
            g_nrep[nidx*HX + (size_t)dir*HHX + j] = hv;
        }
        __syncthreads();
        p ^= 1;
    }
}

// ---------------- padding row + zero row N of hidden buffers ----------------
__global__ void k_pad_zero(const float* __restrict__ pad)
{
    int j = threadIdx.x;
    if (j < HX) {
        g_nrep[(size_t)NX*HX + j] = pad[j];
        g_hid[0][0][(size_t)NX*HX + j] = 0.f;
        g_hid[0][1][(size_t)NX*HX + j] = 0.f;
        g_hid[1][0][(size_t)NX*HX + j] = 0.f;
        g_hid[1][1][(size_t)NX*HX + j] = 0.f;
    }
}

// ---------------- initial hidden = node_repres[batch_nodes] ----------------
__global__ void k_init_hid(const int* __restrict__ nodes)
{
    int idx = blockIdx.x * blockDim.x + threadIdx.x;
    if (idx >= NX*HX) return;
    int n = idx >> 9, cc = idx & (HX - 1);
    float v = g_nrep[(size_t)nodes[n]*HX + cc];
    g_hid[0][0][idx] = v;
    g_hid[1][0][idx] = v;
}

// ------- gather + mean + concat -> bf16 hi/lo cat; optional len compute ----
__global__ __launch_bounds__(128) void k_gm(
    const float* __restrict__ selfT, size_t sSelf,
    const float* __restrict__ neighT, size_t sNeigh,
    const int* __restrict__ nodes,
    const int* __restrict__ adjF, const int* __restrict__ adjB,
    int computeLen)
{
    const int n = blockIdx.x;
    const int dir = blockIdx.y;
    selfT  += (size_t)dir*sSelf;
    neighT += (size_t)dir*sNeigh;
    const int* adj = dir ? adjB : adjF;
    __nv_bfloat16* cath = g_cath[dir];
    __nv_bfloat16* catl = g_catl[dir];

    const int t = threadIdx.x;
    __shared__ int nb[SX];
    __shared__ float s_red[4][SX];
    __shared__ float s_inv;
    if (t < SX) nb[t] = adj[(size_t)nodes[n]*SX + t];
    if (!computeLen && t == 0) s_inv = 1.f / g_len[dir][n];
    __syncthreads();

    const int c = t * 4;
    float4 s = {0.f, 0.f, 0.f, 0.f};
    float rq[SX];
#pragma unroll
    for (int q = 0; q < SX; q++) {
        const float4 v = *(const float4*)&neighT[(size_t)nb[q]*HX + c];
        s.x += v.x; s.y += v.y; s.z += v.z; s.w += v.w;
        if (computeLen) {
            rq[q] = fmaxf(v.x, 0.f) + fmaxf(v.y, 0.f)
                  + fmaxf(v.z, 0.f) + fmaxf(v.w, 0.f);
        }
    }
    if (computeLen) {
        const int lane = t & 31, w = t >> 5;
#pragma unroll
        for (int q = 0; q < SX; q++) {
            float x = rq[q];
#pragma unroll
            for (int o = 16; o; o >>= 1) x += __shfl_xor_sync(0xffffffffu, x, o);
            if (lane == 0) s_red[w][q] = x;
        }
        __syncthreads();
        if (t == 0) {
            float cnt = 0.f;
#pragma unroll
            for (int q = 0; q < SX; q++) {
                float tot = s_red[0][q] + s_red[1][q] + s_red[2][q] + s_red[3][q];
                if (tot > 0.f) cnt += 1.f;
            }
            g_len[dir][n] = cnt;
            s_inv = 1.f / cnt;
        }
        __syncthreads();
    }
    const float invlen = s_inv;

    float4 sv = *(const float4*)&selfT[(size_t)n*HX + c];
    float4 m = {s.x*invlen, s.y*invlen, s.z*invlen, s.w*invlen};

    size_t o = (size_t)n*K_SAGE + c;
    __nv_bfloat16 h0,l0,h1,l1,h2,l2,h3,l3;
    bsplit(sv.x,h0,l0); bsplit(sv.y,h1,l1); bsplit(sv.z,h2,l2); bsplit(sv.w,h3,l3);
    *(__nv_bfloat162*)&cath[o]   = __halves2bfloat162(h0,h1);
    *(__nv_bfloat162*)&cath[o+2] = __halves2bfloat162(h2,h3);
    *(__nv_bfloat162*)&catl[o]   = __halves2bfloat162(l0,l1);
    *(__nv_bfloat162*)&catl[o+2] = __halves2bfloat162(l2,l3);

    bsplit(m.x,h0,l0); bsplit(m.y,h1,l1); bsplit(m.z,h2,l2); bsplit(m.w,h3,l3);
    *(__nv_bfloat162*)&cath[o+HX]   = __halves2bfloat162(h0,h1);
    *(__nv_bfloat162*)&cath[o+HX+2] = __halves2bfloat162(h2,h3);
    *(__nv_bfloat162*)&catl[o+HX]   = __halves2bfloat162(l0,l1);
    *(__nv_bfloat162*)&catl[o+HX+2] = __halves2bfloat162(l2,l3);
}

// ---------------- finalize + pool ----------------
__global__ void k_finalize(float* __restrict__ out, int fin)
{
    int idx = blockIdx.x * blockDim.x + threadIdx.x;
    if (idx >= NX*HX) return;
    int n = idx >> 9, cc = idx & (HX - 1);
    out[(size_t)n*1024 + cc]       = g_hid[0][fin][idx];
    out[(size_t)n*1024 + 512 + cc] = g_hid[1][fin][idx];
    out[(size_t)OFF_OV + idx]      = g_nrep[idx];
}

__global__ void k_pool(const float* __restrict__ hid, float* __restrict__ ge)
{
    const int b = blockIdx.x;
    const int jx = threadIdx.x;
    float m = -3.402823466e38f;
    const float* base = hid + (size_t)b*LX*1024 + jx;
    for (int l = 0; l < LX; l++) m = fmaxf(m, base[(size_t)l*1024]);
    ge[(size_t)b*1024 + jx] = m;
}

// ============================ host launcher ================================
extern "C" void kernel_launch(void* const* d_in, const int* in_sizes, int n_in,
                              void* d_out, int out_size)
{
    const int*   feature_info = (const int*)d_in[0];
    const int*   batch_nodes  = (const int*)d_in[1];
    const int*   fw_adj       = (const int*)d_in[2];
    const int*   bw_adj       = (const int*)d_in[3];
    const float* W_emb        = (const float*)d_in[4];
    const float* Wih_f        = (const float*)d_in[5];
    const float* Whh_f        = (const float*)d_in[6];
    const float* bih_f        = (const float*)d_in[7];
    const float* bhh_f        = (const float*)d_in[8];
    const float* Wih_b        = (const float*)d_in[9];
    const float* Whh_b        = (const float*)d_in[10];
    const float* bih_b        = (const float*)d_in[11];
    const float* bhh_b        = (const float*)d_in[12];
    const float* padding_vec  = (const float*)d_in[13];
    const float* fw_W         = (const float*)d_in[14];
    const float* fw_b         = (const float*)d_in[15];
    const float* bw_W         = (const float*)d_in[16];
    const float* bw_b         = (const float*)d_in[17];
    float* out = (float*)d_out;

    const int DSMEM = 3*65536 + 1024;
    cudaFuncSetAttribute(k_mma_gemm, cudaFuncAttributeMaxDynamicSharedMemorySize, DSMEM);

    float *p_nrep, *p_hid, *p_bias, *p_sbias, *p_xp;
    __nv_bfloat16 *p_embh, *p_embl, *p_wihh, *p_wihl, *p_wh, *p_wl, *p_cath, *p_catl;
    cudaGetSymbolAddress((void**)&p_nrep, g_nrep);
    cudaGetSymbolAddress((void**)&p_hid,  g_hid);
    cudaGetSymbolAddress((void**)&p_bias, g_bias);
    cudaGetSymbolAddress((void**)&p_sbias,g_sbias);
    cudaGetSymbolAddress((void**)&p_xp,   g_xp);
    cudaGetSymbolAddress((void**)&p_embh, g_embh);
    cudaGetSymbolAddress((void**)&p_embl, g_embl);
    cudaGetSymbolAddress((void**)&p_wihh, g_wihh);
    cudaGetSymbolAddress((void**)&p_wihl, g_wihl);
    cudaGetSymbolAddress((void**)&p_wh,   g_wh);
    cudaGetSymbolAddress((void**)&p_wl,   g_wl);
    cudaGetSymbolAddress((void**)&p_cath, g_cath);
    cudaGetSymbolAddress((void**)&p_catl, g_catl);

    const size_t HIDQ = (size_t)(NX+1)*HX;
    const size_t HIDD = 2*HIDQ;
    float* hid_d[2][2];
    for (int d = 0; d < 2; d++)
        for (int q = 0; q < 2; q++)
            hid_d[d][q] = p_hid + ((size_t)d*2 + q)*HIDQ;

    // 1. embed + weight preprocessing (SAGE weight split deferred into LSTM)
    k_embed<<<(NX*EMBP + 255)/256, 256>>>(feature_info, W_emb);
    k_bias<<<(LAYERSX*HX + 255)/256, 256>>>(bih_f, bhh_f, bih_b, bhh_b, fw_b, bw_b);
    k_split_wih<<<(2*1024*EMBP + 255)/256, 256>>>(Wih_f, Wih_b);
    k_whhq<<<(2*HHX*HHX + 255)/256, 256>>>(Whh_f, Whh_b);

    // 2. input projections, both dirs in one launch (bf16x3 mma)
    dim3 gxp(1024/128, NX/128, 2);
    k_mma_gemm<<<gxp, 256, DSMEM>>>(p_embh, p_embl, p_wihh, p_wihl,
                                    p_bias, p_xp, 1024, EMBP, 0,
                                    0, (size_t)1024*EMBP, 1024, (size_t)NX*1024);

    // 3. persistent BiLSTM (blocks 0-63) + concurrent SAGE weight split
    k_lstm<<<64 + NB_SAGEW, 256>>>(fw_W, bw_W);

    // 4. padding row / zero rows / init hidden
    k_pad_zero<<<1, 512>>>(padding_vec);
    k_init_hid<<<(NX*HX + 255)/256, 256>>>(batch_nodes);

    // 5. 7 SAGE layers, both dirs per launch; layer 0 fuses len computation
    int pin = 0;
    dim3 ggm(NX, 2);
    dim3 gsage(HX/128, NX/128, 2);
    for (int l = 0; l < LAYERSX; l++) {
        if (l == 0)
            k_gm<<<ggm, 128>>>(hid_d[0][pin], HIDD, p_nrep, 0,
                               batch_nodes, fw_adj, bw_adj, 1);
        else
            k_gm<<<ggm, 128>>>(hid_d[0][pin], HIDD, hid_d[0][pin], HIDD,
                               batch_nodes, fw_adj, bw_adj, 0);
        k_mma_gemm<<<gsage, 256, DSMEM>>>(
            p_cath, p_catl,
            p_wh + (size_t)l*HX*K_SAGE, p_wl + (size_t)l*HX*K_SAGE,
            p_sbias + (size_t)l*HX, hid_d[0][1 - pin],
            HX, K_SAGE, 1,
            (size_t)NX*K_SAGE, (size_t)LAYERSX*HX*K_SAGE,
            (size_t)LAYERSX*HX, HIDD);
        pin ^= 1;
    }

    // 6. outputs
    k_finalize<<<(NX*HX + 255)/256, 256>>>(out, pin);
    k_pool<<<BX, 1024>>>(out, out + OFF_GE);
    (void)in_sizes; (void)n_in; (void)out_size;
}

// round 16
// speedup vs baseline: 1.2559x; 1.2282x over previous
#include <cuda_runtime.h>
#include <cuda_bf16.h>
#include <math.h>
#include <stdint.h>

#define EMBX 300
#define EMBP 320
#define HX 512
#define HHX 256
#define BX 128
#define LX 128
#define NX (BX*LX)          /* 16384 */
#define SX 10
#define LAYERSX 7
#define K_SAGE 1024

#define SZ_HID (NX*2*HX)
#define OFF_GE SZ_HID
#define OFF_OV (SZ_HID + 2*BX*HX)

// ---------------- scratch (device globals) ----------------
__device__ __align__(16) __nv_bfloat16 g_embh[(size_t)NX*EMBP];
__device__ __align__(16) __nv_bfloat16 g_embl[(size_t)NX*EMBP];
__device__ __align__(16) __nv_bfloat16 g_wihh[2][(size_t)1024*EMBP];
__device__ __align__(16) __nv_bfloat16 g_wihl[2][(size_t)1024*EMBP];
__device__ __align__(16) __nv_bfloat16 g_wh[2][LAYERSX][(size_t)HX*K_SAGE];
__device__ __align__(16) __nv_bfloat16 g_wl[2][LAYERSX][(size_t)HX*K_SAGE];
__device__ __align__(16) __nv_bfloat16 g_cath[2][(size_t)NX*K_SAGE];
__device__ __align__(16) __nv_bfloat16 g_catl[2][(size_t)NX*K_SAGE];
__device__ __align__(16) float g_xp[2][(size_t)NX*1024];
__device__ __align__(16) float g_nrep[(size_t)(NX+1)*HX];
__device__ __align__(16) float g_hid[2][2][(size_t)(NX+1)*HX];
__device__ __align__(16) float g_len[2][NX];
__device__ __align__(16) float g_bias[2][1024];
__device__ __align__(16) float g_sbias[2][LAYERSX*HX];
__device__ __align__(16) float g_hbc[2][2][BX][HHX];   /* h broadcast ping-pong */
__device__ int g_bcnt;
__device__ int g_bsense;

// ---------------- helpers ----------------
#define SWZ(o) ((o) ^ (((o) >> 3) & 0x70))

__device__ __forceinline__ uint32_t s2u(const void* p) {
    uint32_t a;
    asm("{ .reg .u64 t; cvta.to.shared.u64 t, %1; cvt.u32.u64 %0, t; }"
        : "=r"(a) : "l"(p));
    return a;
}
__device__ __forceinline__ void cpa16(uint32_t d, const void* g) {
    asm volatile("cp.async.cg.shared.global [%0], [%1], 16;" :: "r"(d), "l"(g));
}
__device__ __forceinline__ void ldsm4(uint32_t* r, uint32_t addr) {
    asm volatile("ldmatrix.sync.aligned.m8n8.x4.shared.b16 {%0,%1,%2,%3}, [%4];"
        : "=r"(r[0]), "=r"(r[1]), "=r"(r[2]), "=r"(r[3]) : "r"(addr));
}
__device__ __forceinline__ void mma16816(float* d, const uint32_t* a, const uint32_t* b) {
    asm volatile("mma.sync.aligned.m16n8k16.row.col.f32.bf16.bf16.f32 "
        "{%0,%1,%2,%3}, {%4,%5,%6,%7}, {%8,%9}, {%0,%1,%2,%3};"
        : "+f"(d[0]), "+f"(d[1]), "+f"(d[2]), "+f"(d[3])
        : "r"(a[0]), "r"(a[1]), "r"(a[2]), "r"(a[3]), "r"(b[0]), "r"(b[1]));
}
__device__ __forceinline__ void bsplit(float a, __nv_bfloat16& h, __nv_bfloat16& l) {
    h = __float2bfloat16(a);
    l = __float2bfloat16(a - __bfloat162float(h));
}
__device__ __forceinline__ float fsig(float x) {
    return __fdividef(1.f, 1.f + __expf(-x));
}
__device__ __forceinline__ float ftanh(float x) {
    float e = __expf(-2.f*x);
    return __fdividef(1.f - e, 1.f + e);
}

// ---------------- embedding lookup -> bf16 hi/lo, K padded to 320 ----------
__global__ void k_embed(const int* __restrict__ feat, const float* __restrict__ Wemb)
{
    int idx = blockIdx.x * blockDim.x + threadIdx.x;
    if (idx >= NX*EMBP) return;
    int n = idx / EMBP, e = idx - n*EMBP;
    float v = 0.f;
    if (e < EMBX) v = Wemb[(size_t)feat[n]*EMBX + e];
    __nv_bfloat16 h, l; bsplit(v, h, l);
    g_embh[idx] = h; g_embl[idx] = l;
}

// ---------------- bias precompute ----------------
__global__ void k_bias(const float* bihf, const float* bhhf,
                       const float* bihb, const float* bhhb,
                       const float* fwb, const float* bwb)
{
    int j = blockIdx.x * blockDim.x + threadIdx.x;
    if (j < 4*HHX) {
        g_bias[0][j] = bihf[j] + bhhf[j];
        g_bias[1][j] = bihb[j] + bhhb[j];
    }
    if (j < LAYERSX*HX) {
        g_sbias[0][j] = fwb[j];
        g_sbias[1][j] = bwb[j];
    }
}

// ---------------- Wih split -> bf16 hi/lo, padded to 320 -------------------
__global__ void k_split_wih(const float* __restrict__ Wf, const float* __restrict__ Wb)
{
    int idx = blockIdx.x * blockDim.x + threadIdx.x;
    if (idx >= 2*1024*EMBP) return;
    int d = idx / (1024*EMBP);
    int rem = idx - d*(1024*EMBP);
    int r = rem / EMBP, e = rem - r*EMBP;
    const float* W = d ? Wb : Wf;
    float v = (e < EMBX) ? W[(size_t)r*EMBX + e] : 0.f;
    __nv_bfloat16 h, l; bsplit(v, h, l);
    g_wihh[d][rem] = h; g_wihl[d][rem] = l;
}

// ============ mma.sync bf16x3 GEMM (unchanged, proven) =====================
__device__ __forceinline__ void load_stage(
    uint32_t sb, int s, int kc,
    const char* A0, const char* A1, const char* B0, const char* B1,
    int K, int tid)
{
    const char* srcs[4] = { A0, A1, B0, B1 };
    uint32_t stb = sb + s*65536;
#pragma unroll
    for (int t4 = 0; t4 < 4; t4++) {
        const char* src = srcs[t4] + (size_t)kc*128;
        uint32_t tb = stb + t4*16384;
#pragma unroll
        for (int i = 0; i < 4; i++) {
            int q = tid + i*256;
            int r = q >> 3, sc = q & 7;
            cpa16(tb + SWZ(r*128 + sc*16), src + (size_t)r*(size_t)K*2 + sc*16);
        }
    }
    asm volatile("cp.async.commit_group;" ::: "memory");
}

__global__ __launch_bounds__(256, 1) void k_mma_gemm(
    const __nv_bfloat16* __restrict__ Ah, const __nv_bfloat16* __restrict__ Al,
    const __nv_bfloat16* __restrict__ Bh, const __nv_bfloat16* __restrict__ Bl,
    const float* __restrict__ bias, float* __restrict__ C,
    int Ncols, int K, int relu,
    size_t sA, size_t sB, size_t sBias, size_t sC)
{
    extern __shared__ char dsm[];
    const int z = blockIdx.z;
    Ah += (size_t)z*sA;  Al += (size_t)z*sA;
    Bh += (size_t)z*sB;  Bl += (size_t)z*sB;
    bias += (size_t)z*sBias;
    C  += (size_t)z*sC;

    const int tid = threadIdx.x;
    const int wid = tid >> 5, lane = tid & 31;
    const int row0 = blockIdx.y << 7;
    const int col0 = blockIdx.x << 7;
    const int nch = K >> 6;

    uint32_t sb = s2u(dsm);
    sb = (sb + 1023u) & ~1023u;

    const char* A0 = (const char*)(Ah + (size_t)row0*K);
    const char* A1 = (const char*)(Al + (size_t)row0*K);
    const char* B0 = (const char*)(Bh + (size_t)col0*K);
    const char* B1 = (const char*)(Bl + (size_t)col0*K);

    const int wm = (wid >> 1) * 32;
    const int wn = (wid & 1) * 64;
    const int gq8 = lane >> 3, lr = lane & 7;
    const int a_row = wm + lr + ((gq8 & 1) << 3);
    const int a_cb  = (gq8 >> 1) << 4;
    const int b_row = wn + lr + ((gq8 >> 1) << 3);
    const int b_cb  = (gq8 & 1) << 4;

    float acc[2][8][4];
#pragma unroll
    for (int mt = 0; mt < 2; mt++)
#pragma unroll
        for (int nt = 0; nt < 8; nt++)
#pragma unroll
            for (int j = 0; j < 4; j++) acc[mt][nt][j] = 0.f;

    load_stage(sb, 0, 0, A0, A1, B0, B1, K, tid);
    if (nch > 1) load_stage(sb, 1, 1, A0, A1, B0, B1, K, tid);

    int sidx = 0;
    for (int kc = 0; kc < nch; kc++) {
        if (kc + 1 < nch)
            asm volatile("cp.async.wait_group 1;" ::: "memory");
        else
            asm volatile("cp.async.wait_group 0;" ::: "memory");
        __syncthreads();
        if (kc + 2 < nch) {
            int ls = sidx + 2; if (ls >= 3) ls -= 3;
            load_stage(sb, ls, kc + 2, A0, A1, B0, B1, K, tid);
        }
        const uint32_t stb = sb + sidx*65536;
#pragma unroll
        for (int ks = 0; ks < 4; ks++) {
            const int k0b = ks * 32;
            uint32_t ah[2][4], al[2][4];
#pragma unroll
            for (int mt = 0; mt < 2; mt++) {
                uint32_t off = SWZ((uint32_t)((a_row + mt*16)*128 + (a_cb + k0b)));
                ldsm4(ah[mt], stb + off);
                ldsm4(al[mt], stb + 16384 + off);
            }
            uint32_t bh[4][4], bl[4][4];
#pragma unroll
            for (int gg = 0; gg < 4; gg++) {
                uint32_t off = SWZ((uint32_t)((b_row + gg*16)*128 + (b_cb + k0b)));
                ldsm4(bh[gg], stb + 32768 + off);
                ldsm4(bl[gg], stb + 49152 + off);
            }
#pragma unroll
            for (int mt = 0; mt < 2; mt++)
#pragma unroll
                for (int nt = 0; nt < 8; nt++) {
                    const uint32_t* bhp = &bh[nt >> 1][(nt & 1) * 2];
                    const uint32_t* blp = &bl[nt >> 1][(nt & 1) * 2];
                    mma16816(acc[mt][nt], ah[mt], bhp);
                    mma16816(acc[mt][nt], ah[mt], blp);
                    mma16816(acc[mt][nt], al[mt], bhp);
                }
        }
        sidx++; if (sidx >= 3) sidx = 0;
    }

    const int erow = row0 + wm + (lane >> 2);
    const int ecol = col0 + wn + 2*(lane & 3);
#pragma unroll
    for (int mt = 0; mt < 2; mt++)
#pragma unroll
        for (int nt = 0; nt < 8; nt++) {
            int r = erow + mt*16;
            int cc = ecol + nt*8;
            float2 v0, v1;
            v0.x = acc[mt][nt][0] + bias[cc];
            v0.y = acc[mt][nt][1] + bias[cc+1];
            v1.x = acc[mt][nt][2] + bias[cc];
            v1.y = acc[mt][nt][3] + bias[cc+1];
            if (relu) {
                v0.x = fmaxf(v0.x, 0.f); v0.y = fmaxf(v0.y, 0.f);
                v1.x = fmaxf(v1.x, 0.f); v1.y = fmaxf(v1.y, 0.f);
            }
            *(float2*)&C[(size_t)r*Ncols + cc]     = v0;
            *(float2*)&C[(size_t)(r+8)*Ncols + cc] = v1;
        }
}

// ================= tensor-core persistent BiLSTM ===========================
// Blocks 0-31: 2 dirs x 2 rowhalves(64 seqs) x 8 gate-col slices (32 h-cols).
// W slice (256k x 128n bf16 hi/lo) resident in smem for all 128 steps.
// A (h) rebuilt per step from gmem broadcast; xp preloaded into accumulators.
// Blocks >=32: SAGE weight split (16 elems/thread).
#define NB_SPLIT 1792        /* 1792*256*16 = 7340032 = 2*7*512*1024 */
#define SMA_H 0
#define SMA_L 32768
#define SMB_H 65536
#define SMB_L 131072
#define SMGT  196608
#define LSTM_SMEM 229376

__device__ __forceinline__ uint32_t offA(int row, int ke) {
    uint32_t o = (uint32_t)((((ke >> 6)*8 + (row >> 3))<<10) + ((row & 7)<<7) + ((ke & 63)<<1));
    return SWZ(o);
}
__device__ __forceinline__ uint32_t offB(int n, int ke) {
    uint32_t o = (uint32_t)((((ke >> 6)*16 + (n >> 3))<<10) + ((n & 7)<<7) + ((ke & 63)<<1));
    return SWZ(o);
}

__global__ __launch_bounds__(256, 1) void k_lstm(
    const float* __restrict__ Whhf, const float* __restrict__ Whhb,
    const float* __restrict__ fwW, const float* __restrict__ bwW)
{
    const int bx = blockIdx.x;
    const int tid = threadIdx.x;
    if (bx >= 32) {
        const int per = LAYERSX*HX*K_SAGE;
        int base = (bx - 32)*4096 + tid;
#pragma unroll
        for (int i = 0; i < 16; i++) {
            int idx = base + i*256;
            int d = idx / per, rem = idx - d*per;
            float v = (d ? bwW : fwW)[rem];
            __nv_bfloat16 h, l; bsplit(v, h, l);
            (&g_wh[0][0][0])[(size_t)d*per + rem] = h;
            (&g_wl[0][0][0])[(size_t)d*per + rem] = l;
        }
        return;
    }
    extern __shared__ char sm[];
    const uint32_t sb = s2u(sm);
    const int dir = bx >> 4;
    const int rh  = (bx >> 3) & 1;
    const int jc  = bx & 7;
    const int wid = tid >> 5, lane = tid & 31;
    const float* __restrict__ Whh = dir ? Whhb : Whhf;
    const float* __restrict__ xp = g_xp[dir];

    // ---- load W slice into smem (blocked atoms, bf16 hi/lo) ----
    {
        const int n = tid >> 1;
        const int kh = (tid & 1) * 128;
        const int gr = (n >> 5)*HHX + jc*32 + (n & 31);
        const float* wrow = Whh + (size_t)gr*HHX + kh;
#pragma unroll 8
        for (int kk = 0; kk < 128; kk += 4) {
            float4 v = *(const float4*)&wrow[kk];
            __nv_bfloat16 h0,l0,h1,l1,h2,l2,h3,l3;
            bsplit(v.x,h0,l0); bsplit(v.y,h1,l1);
            bsplit(v.z,h2,l2); bsplit(v.w,h3,l3);
            uint32_t o = offB(n, kh + kk);
            *(__nv_bfloat162*)(sm + SMB_H + o)     = __halves2bfloat162(h0,h1);
            *(__nv_bfloat162*)(sm + SMB_H + o + 4) = __halves2bfloat162(h2,h3);
            *(__nv_bfloat162*)(sm + SMB_L + o)     = __halves2bfloat162(l0,l1);
            *(__nv_bfloat162*)(sm + SMB_L + o + 4) = __halves2bfloat162(l2,l3);
        }
    }
    // ---- zero my slice of hbc[0] + init c-state ----
    {
        const int jj = tid & 31, r0 = (tid >> 5) * 8;
#pragma unroll
        for (int rr = 0; rr < 8; rr++)
            g_hbc[0][dir][rh*64 + r0 + rr][jc*32 + jj] = 0.f;
    }
    float cst[8];
#pragma unroll
    for (int i = 0; i < 8; i++) cst[i] = 0.f;
    __syncthreads();

    // warp tiling: wm = row tile (16), wn = col half (64)
    const int wm = (wid >> 1) * 16;
    const int wn = (wid & 1) * 64;
    const int gq8 = lane >> 3, lr = lane & 7;
    const int arow = wm + lr + ((gq8 & 1) << 3);
    const int ake  = (gq8 >> 1) << 3;
    const int brow = lr + ((gq8 >> 1) << 3);
    const int bke  = (gq8 & 1) << 3;

    int bs = 0, p = 0;
    // initial barrier (hbc[0] zeroed by all blocks)
    {
        bs++;
        __threadfence();
        __syncthreads();
        if (tid == 0) {
            int old = atomicAdd(&g_bcnt, 1);
            if (old == 31) { atomicExch(&g_bcnt, 0); __threadfence(); atomicExch(&g_bsense, bs); }
            else { while (atomicAdd(&g_bsense, 0) != bs) ; }
        }
        __syncthreads();
    }

    for (int t = 0; t < LX; t++) {
        const int tseq = dir ? (LX - 1 - t) : t;
        // ---- 1. xp preload into accumulators ----
        float acc[8][4];
        {
            const int rl0 = wm + (lane >> 2);
            const size_t nib0 = ((size_t)(rh*64 + rl0)*LX + tseq) * 1024;
            const size_t nib1 = nib0 + (size_t)8*LX*1024;
#pragma unroll
            for (int nt = 0; nt < 8; nt++) {
                int n0 = wn + nt*8 + 2*(lane & 3);
                int gcol = (n0 >> 5)*HHX + jc*32 + (n0 & 31);
                float2 v0 = *(const float2*)&xp[nib0 + gcol];
                float2 v1 = *(const float2*)&xp[nib1 + gcol];
                acc[nt][0] = v0.x; acc[nt][1] = v0.y;
                acc[nt][2] = v1.x; acc[nt][3] = v1.y;
            }
        }
        // ---- 2. build A smem from hbc[p] ----
        {
            const int rl = tid >> 2;
            const int q0 = (tid & 3) * 16;
            const float* hrow = &g_hbc[p][dir][rh*64 + rl][0];
#pragma unroll 4
            for (int i = 0; i < 16; i++) {
                int c = (q0 + i) * 4;
                float4 v = *(const float4*)&hrow[c];
                __nv_bfloat16 h0,l0,h1,l1,h2,l2,h3,l3;
                bsplit(v.x,h0,l0); bsplit(v.y,h1,l1);
                bsplit(v.z,h2,l2); bsplit(v.w,h3,l3);
                uint32_t o = offA(rl, c);
                *(__nv_bfloat162*)(sm + SMA_H + o)     = __halves2bfloat162(h0,h1);
                *(__nv_bfloat162*)(sm + SMA_H + o + 4) = __halves2bfloat162(h2,h3);
                *(__nv_bfloat162*)(sm + SMA_L + o)     = __halves2bfloat162(l0,l1);
                *(__nv_bfloat162*)(sm + SMA_L + o + 4) = __halves2bfloat162(l2,l3);
            }
        }
        __syncthreads();
        // ---- 3. MMA over k = 256 (bf16x3) ----
#pragma unroll 4
        for (int k0 = 0; k0 < 256; k0 += 16) {
            uint32_t ah[4], al[4];
            uint32_t oa = offA(arow, k0 + ake);
            ldsm4(ah, sb + SMA_H + oa);
            ldsm4(al, sb + SMA_L + oa);
            uint32_t bh[4][4], bl[4][4];
#pragma unroll
            for (int gg = 0; gg < 4; gg++) {
                uint32_t ob = offB(wn + gg*16 + brow, k0 + bke);
                ldsm4(bh[gg], sb + SMB_H + ob);
                ldsm4(bl[gg], sb + SMB_L + ob);
            }
#pragma unroll
            for (int nt = 0; nt < 8; nt++) {
                const uint32_t* bhp = &bh[nt >> 1][(nt & 1) * 2];
                const uint32_t* blp = &bl[nt >> 1][(nt & 1) * 2];
                mma16816(acc[nt], ah, bhp);
                mma16816(acc[nt], ah, blp);
                mma16816(acc[nt], al, bhp);
            }
        }
        // ---- 4. store gate pre-activations to smem ----
        {
            float* gbuf = (float*)(sm + SMGT);
            const int r0 = wm + (lane >> 2);
#pragma unroll
            for (int nt = 0; nt < 8; nt++) {
                int cc = wn + nt*8 + 2*(lane & 3);
                *(float2*)&gbuf[(size_t)r0*128 + cc]     = make_float2(acc[nt][0], acc[nt][1]);
                *(float2*)&gbuf[(size_t)(r0+8)*128 + cc] = make_float2(acc[nt][2], acc[nt][3]);
            }
        }
        __syncthreads();
        // ---- 5. gate math -> h; publish ----
        {
            const float* gbuf = (const float*)(sm + SMGT);
            const int jj = tid & 31, r0 = (tid >> 5) * 8;
#pragma unroll
            for (int rr = 0; rr < 8; rr++) {
                const int row = r0 + rr;
                float gi = gbuf[(size_t)row*128 + jj];
                float gf = gbuf[(size_t)row*128 + 32 + jj];
                float gg = gbuf[(size_t)row*128 + 64 + jj];
                float go = gbuf[(size_t)row*128 + 96 + jj];
                float si = fsig(gi), sf = fsig(gf), so = fsig(go);
                float tg = ftanh(gg);
                cst[rr] = sf*cst[rr] + si*tg;
                float hv = so * ftanh(cst[rr]);
                const int seqr = rh*64 + row;
                const size_t nidx = (size_t)seqr*LX + tseq;
                g_nrep[nidx*HX + (size_t)dir*HHX + jc*32 + jj] = hv;
                g_hbc[p ^ 1][dir][seqr][jc*32 + jj] = hv;
            }
        }
        // ---- 6. barrier ----
        bs++;
        __threadfence();
        __syncthreads();
        if (tid == 0) {
            int old = atomicAdd(&g_bcnt, 1);
            if (old == 31) { atomicExch(&g_bcnt, 0); __threadfence(); atomicExch(&g_bsense, bs); }
            else { while (atomicAdd(&g_bsense, 0) != bs) ; }
        }
        __syncthreads();
        p ^= 1;
    }
}

// ---------------- padding row + zero row N of hidden buffers ----------------
__global__ void k_pad_zero(const float* __restrict__ pad)
{
    int j = threadIdx.x;
    if (j < HX) {
        g_nrep[(size_t)NX*HX + j] = pad[j];
        g_hid[0][0][(size_t)NX*HX + j] = 0.f;
        g_hid[0][1][(size_t)NX*HX + j] = 0.f;
        g_hid[1][0][(size_t)NX*HX + j] = 0.f;
        g_hid[1][1][(size_t)NX*HX + j] = 0.f;
    }
}

// ---------------- initial hidden = node_repres[batch_nodes] ----------------
__global__ void k_init_hid(const int* __restrict__ nodes)
{
    int idx = blockIdx.x * blockDim.x + threadIdx.x;
    if (idx >= NX*HX) return;
    int n = idx >> 9, cc = idx & (HX - 1);
    float v = g_nrep[(size_t)nodes[n]*HX + cc];
    g_hid[0][0][idx] = v;
    g_hid[1][0][idx] = v;
}

// ------- gather + mean + concat -> bf16 hi/lo cat; optional len compute ----
__global__ __launch_bounds__(128) void k_gm(
    const float* __restrict__ selfT, size_t sSelf,
    const float* __restrict__ neighT, size_t sNeigh,
    const int* __restrict__ nodes,
    const int* __restrict__ adjF, const int* __restrict__ adjB,
    int computeLen)
{
    const int n = blockIdx.x;
    const int dir = blockIdx.y;
    selfT  += (size_t)dir*sSelf;
    neighT += (size_t)dir*sNeigh;
    const int* adj = dir ? adjB : adjF;
    __nv_bfloat16* cath = g_cath[dir];
    __nv_bfloat16* catl = g_catl[dir];

    const int t = threadIdx.x;
    __shared__ int nb[SX];
    __shared__ float s_red[4][SX];
    __shared__ float s_inv;
    if (t < SX) nb[t] = adj[(size_t)nodes[n]*SX + t];
    if (!computeLen && t == 0) s_inv = 1.f / g_len[dir][n];
    __syncthreads();

    const int c = t * 4;
    float4 s = {0.f, 0.f, 0.f, 0.f};
    float rq[SX];
#pragma unroll
    for (int q = 0; q < SX; q++) {
        const float4 v = *(const float4*)&neighT[(size_t)nb[q]*HX + c];
        s.x += v.x; s.y += v.y; s.z += v.z; s.w += v.w;
        if (computeLen) {
            rq[q] = fmaxf(v.x, 0.f) + fmaxf(v.y, 0.f)
                  + fmaxf(v.z, 0.f) + fmaxf(v.w, 0.f);
        }
    }
    if (computeLen) {
        const int lane = t & 31, w = t >> 5;
#pragma unroll
        for (int q = 0; q < SX; q++) {
            float x = rq[q];
#pragma unroll
            for (int o = 16; o; o >>= 1) x += __shfl_xor_sync(0xffffffffu, x, o);
            if (lane == 0) s_red[w][q] = x;
        }
        __syncthreads();
        if (t == 0) {
            float cnt = 0.f;
#pragma unroll
            for (int q = 0; q < SX; q++) {
                float tot = s_red[0][q] + s_red[1][q] + s_red[2][q] + s_red[3][q];
                if (tot > 0.f) cnt += 1.f;
            }
            g_len[dir][n] = cnt;
            s_inv = 1.f / cnt;
        }
        __syncthreads();
    }
    const float invlen = s_inv;

    float4 sv = *(const float4*)&selfT[(size_t)n*HX + c];
    float4 m = {s.x*invlen, s.y*invlen, s.z*invlen, s.w*invlen};

    size_t o = (size_t)n*K_SAGE + c;
    __nv_bfloat16 h0,l0,h1,l1,h2,l2,h3,l3;
    bsplit(sv.x,h0,l0); bsplit(sv.y,h1,l1); bsplit(sv.z,h2,l2); bsplit(sv.w,h3,l3);
    *(__nv_bfloat162*)&cath[o]   = __halves2bfloat162(h0,h1);
    *(__nv_bfloat162*)&cath[o+2] = __halves2bfloat162(h2,h3);
    *(__nv_bfloat162*)&catl[o]   = __halves2bfloat162(l0,l1);
    *(__nv_bfloat162*)&catl[o+2] = __halves2bfloat162(l2,l3);

    bsplit(m.x,h0,l0); bsplit(m.y,h1,l1); bsplit(m.z,h2,l2); bsplit(m.w,h3,l3);
    *(__nv_bfloat162*)&cath[o+HX]   = __halves2bfloat162(h0,h1);
    *(__nv_bfloat162*)&cath[o+HX+2] = __halves2bfloat162(h2,h3);
    *(__nv_bfloat162*)&catl[o+HX]   = __halves2bfloat162(l0,l1);
    *(__nv_bfloat162*)&catl[o+HX+2] = __halves2bfloat162(l2,l3);
}

// ---------------- finalize + pool ----------------
__global__ void k_finalize(float* __restrict__ out, int fin)
{
    int idx = blockIdx.x * blockDim.x + threadIdx.x;
    if (idx >= NX*HX) return;
    int n = idx >> 9, cc = idx & (HX - 1);
    out[(size_t)n*1024 + cc]       = g_hid[0][fin][idx];
    out[(size_t)n*1024 + 512 + cc] = g_hid[1][fin][idx];
    out[(size_t)OFF_OV + idx]      = g_nrep[idx];
}

__global__ void k_pool(const float* __restrict__ hid, float* __restrict__ ge)
{
    const int b = blockIdx.x;
    const int jx = threadIdx.x;
    float m = -3.402823466e38f;
    const float* base = hid + (size_t)b*LX*1024 + jx;
    for (int l = 0; l < LX; l++) m = fmaxf(m, base[(size_t)l*1024]);
    ge[(size_t)b*1024 + jx] = m;
}

// ============================ host launcher ================================
extern "C" void kernel_launch(void* const* d_in, const int* in_sizes, int n_in,
                              void* d_out, int out_size)
{
    const int*   feature_info = (const int*)d_in[0];
    const int*   batch_nodes  = (const int*)d_in[1];
    const int*   fw_adj       = (const int*)d_in[2];
    const int*   bw_adj       = (const int*)d_in[3];
    const float* W_emb        = (const float*)d_in[4];
    const float* Wih_f        = (const float*)d_in[5];
    const float* Whh_f        = (const float*)d_in[6];
    const float* bih_f        = (const float*)d_in[7];
    const float* bhh_f        = (const float*)d_in[8];
    const float* Wih_b        = (const float*)d_in[9];
    const float* Whh_b        = (const float*)d_in[10];
    const float* bih_b        = (const float*)d_in[11];
    const float* bhh_b        = (const float*)d_in[12];
    const float* padding_vec  = (const float*)d_in[13];
    const float* fw_W         = (const float*)d_in[14];
    const float* fw_b         = (const float*)d_in[15];
    const float* bw_W         = (const float*)d_in[16];
    const float* bw_b         = (const float*)d_in[17];
    float* out = (float*)d_out;

    const int DSMEM = 3*65536 + 1024;
    cudaFuncSetAttribute(k_mma_gemm, cudaFuncAttributeMaxDynamicSharedMemorySize, DSMEM);
    cudaFuncSetAttribute(k_lstm, cudaFuncAttributeMaxDynamicSharedMemorySize, LSTM_SMEM);

    float *p_nrep, *p_hid, *p_bias, *p_sbias, *p_xp;
    __nv_bfloat16 *p_embh, *p_embl, *p_wihh, *p_wihl, *p_wh, *p_wl, *p_cath, *p_catl;
    cudaGetSymbolAddress((void**)&p_nrep, g_nrep);
    cudaGetSymbolAddress((void**)&p_hid,  g_hid);
    cudaGetSymbolAddress((void**)&p_bias, g_bias);
    cudaGetSymbolAddress((void**)&p_sbias,g_sbias);
    cudaGetSymbolAddress((void**)&p_xp,   g_xp);
    cudaGetSymbolAddress((void**)&p_embh, g_embh);
    cudaGetSymbolAddress((void**)&p_embl, g_embl);
    cudaGetSymbolAddress((void**)&p_wihh, g_wihh);
    cudaGetSymbolAddress((void**)&p_wihl, g_wihl);
    cudaGetSymbolAddress((void**)&p_wh,   g_wh);
    cudaGetSymbolAddress((void**)&p_wl,   g_wl);
    cudaGetSymbolAddress((void**)&p_cath, g_cath);
    cudaGetSymbolAddress((void**)&p_catl, g_catl);

    const size_t HIDQ = (size_t)(NX+1)*HX;
    const size_t HIDD = 2*HIDQ;
    float* hid_d[2][2];
    for (int d = 0; d < 2; d++)
        for (int q = 0; q < 2; q++)
            hid_d[d][q] = p_hid + ((size_t)d*2 + q)*HIDQ;

    // 1. embed + weight preprocessing (SAGE split folded into LSTM launch)
    k_embed<<<(NX*EMBP + 255)/256, 256>>>(feature_info, W_emb);
    k_bias<<<(LAYERSX*HX + 255)/256, 256>>>(bih_f, bhh_f, bih_b, bhh_b, fw_b, bw_b);
    k_split_wih<<<(2*1024*EMBP + 255)/256, 256>>>(Wih_f, Wih_b);

    // 2. input projections, both dirs in one launch (bf16x3 mma)
    dim3 gxp(1024/128, NX/128, 2);
    k_mma_gemm<<<gxp, 256, DSMEM>>>(p_embh, p_embl, p_wihh, p_wihl,
                                    p_bias, p_xp, 1024, EMBP, 0,
                                    0, (size_t)1024*EMBP, 1024, (size_t)NX*1024);

    // 3. tensor-core persistent BiLSTM + concurrent SAGE weight split
    k_lstm<<<32 + NB_SPLIT, 256, LSTM_SMEM>>>(Whh_f, Whh_b, fw_W, bw_W);

    // 4. padding row / zero rows / init hidden
    k_pad_zero<<<1, 512>>>(padding_vec);
    k_init_hid<<<(NX*HX + 255)/256, 256>>>(batch_nodes);

    // 5. 7 SAGE layers, both dirs per launch; layer 0 fuses len computation
    int pin = 0;
    dim3 ggm(NX, 2);
    dim3 gsage(HX/128, NX/128, 2);
    for (int l = 0; l < LAYERSX; l++) {
        if (l == 0)
            k_gm<<<ggm, 128>>>(hid_d[0][pin], HIDD, p_nrep, 0,
                               batch_nodes, fw_adj, bw_adj, 1);
        else
            k_gm<<<ggm, 128>>>(hid_d[0][pin], HIDD, hid_d[0][pin], HIDD,
                               batch_nodes, fw_adj, bw_adj, 0);
        k_mma_gemm<<<gsage, 256, DSMEM>>>(
            p_cath, p_catl,
            p_wh + (size_t)l*HX*K_SAGE, p_wl + (size_t)l*HX*K_SAGE,
            p_sbias + (size_t)l*HX, hid_d[0][1 - pin],
            HX, K_SAGE, 1,
            (size_t)NX*K_SAGE, (size_t)LAYERSX*HX*K_SAGE,
            (size_t)LAYERSX*HX, HIDD);
        pin ^= 1;
    }

    // 6. outputs
    k_finalize<<<(NX*HX + 255)/256, 256>>>(out, pin);
    k_pool<<<BX, 1024>>>(out, out + OFF_GE);
    (void)in_sizes; (void)n_in; (void)out_size;
}

// round 17
// speedup vs baseline: 1.2673x; 1.0090x over previous
#include <cuda_runtime.h>
#include <cuda_bf16.h>
#include <math.h>
#include <stdint.h>

#define EMBX 300
#define EMBP 320
#define HX 512
#define HHX 256
#define BX 128
#define LX 128
#define NX (BX*LX)          /* 16384 */
#define SX 10
#define LAYERSX 7
#define K_SAGE 1024

#define SZ_HID (NX*2*HX)
#define OFF_GE SZ_HID
#define OFF_OV (SZ_HID + 2*BX*HX)

// ---------------- scratch (device globals) ----------------
__device__ __align__(16) __nv_bfloat16 g_embh[(size_t)NX*EMBP];
__device__ __align__(16) __nv_bfloat16 g_embl[(size_t)NX*EMBP];
__device__ __align__(16) __nv_bfloat16 g_wihh[2][(size_t)1024*EMBP];
__device__ __align__(16) __nv_bfloat16 g_wihl[2][(size_t)1024*EMBP];
__device__ __align__(16) __nv_bfloat16 g_wh[2][LAYERSX][(size_t)HX*K_SAGE];
__device__ __align__(16) __nv_bfloat16 g_wl[2][LAYERSX][(size_t)HX*K_SAGE];
__device__ __align__(16) __nv_bfloat16 g_cath[2][(size_t)NX*K_SAGE];
__device__ __align__(16) __nv_bfloat16 g_catl[2][(size_t)NX*K_SAGE];
__device__ __align__(16) float g_xp[2][(size_t)NX*1024];
__device__ __align__(16) float g_nrep[(size_t)(NX+1)*HX];
__device__ __align__(16) float g_hid[2][2][(size_t)(NX+1)*HX];
__device__ __align__(16) float g_len[2][NX];
__device__ __align__(16) float g_bias[2][1024];
__device__ __align__(16) float g_sbias[2][LAYERSX*HX];
__device__ __align__(16) float g_hbc[2][2][BX][HHX];   /* h broadcast ping-pong */
__device__ int g_bcnt;
__device__ int g_bsense;

// ---------------- helpers ----------------
#define SWZ(o) ((o) ^ (((o) >> 3) & 0x70))

__device__ __forceinline__ uint32_t s2u(const void* p) {
    uint32_t a;
    asm("{ .reg .u64 t; cvta.to.shared.u64 t, %1; cvt.u32.u64 %0, t; }"
        : "=r"(a) : "l"(p));
    return a;
}
__device__ __forceinline__ void cpa16(uint32_t d, const void* g) {
    asm volatile("cp.async.cg.shared.global [%0], [%1], 16;" :: "r"(d), "l"(g));
}
__device__ __forceinline__ void ldsm4(uint32_t* r, uint32_t addr) {
    asm volatile("ldmatrix.sync.aligned.m8n8.x4.shared.b16 {%0,%1,%2,%3}, [%4];"
        : "=r"(r[0]), "=r"(r[1]), "=r"(r[2]), "=r"(r[3]) : "r"(addr));
}
__device__ __forceinline__ void mma16816(float* d, const uint32_t* a, const uint32_t* b) {
    asm volatile("mma.sync.aligned.m16n8k16.row.col.f32.bf16.bf16.f32 "
        "{%0,%1,%2,%3}, {%4,%5,%6,%7}, {%8,%9}, {%0,%1,%2,%3};"
        : "+f"(d[0]), "+f"(d[1]), "+f"(d[2]), "+f"(d[3])
        : "r"(a[0]), "r"(a[1]), "r"(a[2]), "r"(a[3]), "r"(b[0]), "r"(b[1]));
}
__device__ __forceinline__ void bsplit(float a, __nv_bfloat16& h, __nv_bfloat16& l) {
    h = __float2bfloat16(a);
    l = __float2bfloat16(a - __bfloat162float(h));
}
__device__ __forceinline__ float fsig(float x) {
    return __fdividef(1.f, 1.f + __expf(-x));
}
__device__ __forceinline__ float ftanh(float x) {
    float e = __expf(-2.f*x);
    return __fdividef(1.f - e, 1.f + e);
}

// ---------------- embedding lookup -> bf16 hi/lo, K padded to 320 ----------
__global__ void k_embed(const int* __restrict__ feat, const float* __restrict__ Wemb)
{
    int idx = blockIdx.x * blockDim.x + threadIdx.x;
    if (idx >= NX*EMBP) return;
    int n = idx / EMBP, e = idx - n*EMBP;
    float v = 0.f;
    if (e < EMBX) v = Wemb[(size_t)feat[n]*EMBX + e];
    __nv_bfloat16 h, l; bsplit(v, h, l);
    g_embh[idx] = h; g_embl[idx] = l;
}

// ---------------- bias precompute ----------------
__global__ void k_bias(const float* bihf, const float* bhhf,
                       const float* bihb, const float* bhhb,
                       const float* fwb, const float* bwb)
{
    int j = blockIdx.x * blockDim.x + threadIdx.x;
    if (j < 4*HHX) {
        g_bias[0][j] = bihf[j] + bhhf[j];
        g_bias[1][j] = bihb[j] + bhhb[j];
    }
    if (j < LAYERSX*HX) {
        g_sbias[0][j] = fwb[j];
        g_sbias[1][j] = bwb[j];
    }
}

// ---------------- Wih split -> bf16 hi/lo, padded to 320 -------------------
__global__ void k_split_wih(const float* __restrict__ Wf, const float* __restrict__ Wb)
{
    int idx = blockIdx.x * blockDim.x + threadIdx.x;
    if (idx >= 2*1024*EMBP) return;
    int d = idx / (1024*EMBP);
    int rem = idx - d*(1024*EMBP);
    int r = rem / EMBP, e = rem - r*EMBP;
    const float* W = d ? Wb : Wf;
    float v = (e < EMBX) ? W[(size_t)r*EMBX + e] : 0.f;
    __nv_bfloat16 h, l; bsplit(v, h, l);
    g_wihh[d][rem] = h; g_wihl[d][rem] = l;
}

// ============ mma.sync bf16x3 GEMM (unchanged, proven) =====================
__device__ __forceinline__ void load_stage(
    uint32_t sb, int s, int kc,
    const char* A0, const char* A1, const char* B0, const char* B1,
    int K, int tid)
{
    const char* srcs[4] = { A0, A1, B0, B1 };
    uint32_t stb = sb + s*65536;
#pragma unroll
    for (int t4 = 0; t4 < 4; t4++) {
        const char* src = srcs[t4] + (size_t)kc*128;
        uint32_t tb = stb + t4*16384;
#pragma unroll
        for (int i = 0; i < 4; i++) {
            int q = tid + i*256;
            int r = q >> 3, sc = q & 7;
            cpa16(tb + SWZ(r*128 + sc*16), src + (size_t)r*(size_t)K*2 + sc*16);
        }
    }
    asm volatile("cp.async.commit_group;" ::: "memory");
}

__global__ __launch_bounds__(256, 1) void k_mma_gemm(
    const __nv_bfloat16* __restrict__ Ah, const __nv_bfloat16* __restrict__ Al,
    const __nv_bfloat16* __restrict__ Bh, const __nv_bfloat16* __restrict__ Bl,
    const float* __restrict__ bias, float* __restrict__ C,
    int Ncols, int K, int relu,
    size_t sA, size_t sB, size_t sBias, size_t sC)
{
    extern __shared__ char dsm[];
    const int z = blockIdx.z;
    Ah += (size_t)z*sA;  Al += (size_t)z*sA;
    Bh += (size_t)z*sB;  Bl += (size_t)z*sB;
    bias += (size_t)z*sBias;
    C  += (size_t)z*sC;

    const int tid = threadIdx.x;
    const int wid = tid >> 5, lane = tid & 31;
    const int row0 = blockIdx.y << 7;
    const int col0 = blockIdx.x << 7;
    const int nch = K >> 6;

    uint32_t sb = s2u(dsm);
    sb = (sb + 1023u) & ~1023u;

    const char* A0 = (const char*)(Ah + (size_t)row0*K);
    const char* A1 = (const char*)(Al + (size_t)row0*K);
    const char* B0 = (const char*)(Bh + (size_t)col0*K);
    const char* B1 = (const char*)(Bl + (size_t)col0*K);

    const int wm = (wid >> 1) * 32;
    const int wn = (wid & 1) * 64;
    const int gq8 = lane >> 3, lr = lane & 7;
    const int a_row = wm + lr + ((gq8 & 1) << 3);
    const int a_cb  = (gq8 >> 1) << 4;
    const int b_row = wn + lr + ((gq8 >> 1) << 3);
    const int b_cb  = (gq8 & 1) << 4;

    float acc[2][8][4];
#pragma unroll
    for (int mt = 0; mt < 2; mt++)
#pragma unroll
        for (int nt = 0; nt < 8; nt++)
#pragma unroll
            for (int j = 0; j < 4; j++) acc[mt][nt][j] = 0.f;

    load_stage(sb, 0, 0, A0, A1, B0, B1, K, tid);
    if (nch > 1) load_stage(sb, 1, 1, A0, A1, B0, B1, K, tid);

    int sidx = 0;
    for (int kc = 0; kc < nch; kc++) {
        if (kc + 1 < nch)
            asm volatile("cp.async.wait_group 1;" ::: "memory");
        else
            asm volatile("cp.async.wait_group 0;" ::: "memory");
        __syncthreads();
        if (kc + 2 < nch) {
            int ls = sidx + 2; if (ls >= 3) ls -= 3;
            load_stage(sb, ls, kc + 2, A0, A1, B0, B1, K, tid);
        }
        const uint32_t stb = sb + sidx*65536;
#pragma unroll
        for (int ks = 0; ks < 4; ks++) {
            const int k0b = ks * 32;
            uint32_t ah[2][4], al[2][4];
#pragma unroll
            for (int mt = 0; mt < 2; mt++) {
                uint32_t off = SWZ((uint32_t)((a_row + mt*16)*128 + (a_cb + k0b)));
                ldsm4(ah[mt], stb + off);
                ldsm4(al[mt], stb + 16384 + off);
            }
            uint32_t bh[4][4], bl[4][4];
#pragma unroll
            for (int gg = 0; gg < 4; gg++) {
                uint32_t off = SWZ((uint32_t)((b_row + gg*16)*128 + (b_cb + k0b)));
                ldsm4(bh[gg], stb + 32768 + off);
                ldsm4(bl[gg], stb + 49152 + off);
            }
#pragma unroll
            for (int mt = 0; mt < 2; mt++)
#pragma unroll
                for (int nt = 0; nt < 8; nt++) {
                    const uint32_t* bhp = &bh[nt >> 1][(nt & 1) * 2];
                    const uint32_t* blp = &bl[nt >> 1][(nt & 1) * 2];
                    mma16816(acc[mt][nt], ah[mt], bhp);
                    mma16816(acc[mt][nt], ah[mt], blp);
                    mma16816(acc[mt][nt], al[mt], bhp);
                }
        }
        sidx++; if (sidx >= 3) sidx = 0;
    }

    const int erow = row0 + wm + (lane >> 2);
    const int ecol = col0 + wn + 2*(lane & 3);
#pragma unroll
    for (int mt = 0; mt < 2; mt++)
#pragma unroll
        for (int nt = 0; nt < 8; nt++) {
            int r = erow + mt*16;
            int cc = ecol + nt*8;
            float2 v0, v1;
            v0.x = acc[mt][nt][0] + bias[cc];
            v0.y = acc[mt][nt][1] + bias[cc+1];
            v1.x = acc[mt][nt][2] + bias[cc];
            v1.y = acc[mt][nt][3] + bias[cc+1];
            if (relu) {
                v0.x = fmaxf(v0.x, 0.f); v0.y = fmaxf(v0.y, 0.f);
                v1.x = fmaxf(v1.x, 0.f); v1.y = fmaxf(v1.y, 0.f);
            }
            *(float2*)&C[(size_t)r*Ncols + cc]     = v0;
            *(float2*)&C[(size_t)(r+8)*Ncols + cc] = v1;
        }
}

// ================= tensor-core persistent BiLSTM (R16, proven) =============
#define NB_SPLIT 1792
#define SMA_H 0
#define SMA_L 32768
#define SMB_H 65536
#define SMB_L 131072
#define SMGT  196608
#define LSTM_SMEM 229376

__device__ __forceinline__ uint32_t offA(int row, int ke) {
    uint32_t o = (uint32_t)((((ke >> 6)*8 + (row >> 3))<<10) + ((row & 7)<<7) + ((ke & 63)<<1));
    return SWZ(o);
}
__device__ __forceinline__ uint32_t offB(int n, int ke) {
    uint32_t o = (uint32_t)((((ke >> 6)*16 + (n >> 3))<<10) + ((n & 7)<<7) + ((ke & 63)<<1));
    return SWZ(o);
}

__global__ __launch_bounds__(256, 1) void k_lstm(
    const float* __restrict__ Whhf, const float* __restrict__ Whhb,
    const float* __restrict__ fwW, const float* __restrict__ bwW)
{
    const int bx = blockIdx.x;
    const int tid = threadIdx.x;
    if (bx >= 32) {
        const int per = LAYERSX*HX*K_SAGE;
        int base = (bx - 32)*4096 + tid;
#pragma unroll
        for (int i = 0; i < 16; i++) {
            int idx = base + i*256;
            int d = idx / per, rem = idx - d*per;
            float v = (d ? bwW : fwW)[rem];
            __nv_bfloat16 h, l; bsplit(v, h, l);
            (&g_wh[0][0][0])[(size_t)d*per + rem] = h;
            (&g_wl[0][0][0])[(size_t)d*per + rem] = l;
        }
        return;
    }
    extern __shared__ char sm[];
    const uint32_t sb = s2u(sm);
    const int dir = bx >> 4;
    const int rh  = (bx >> 3) & 1;
    const int jc  = bx & 7;
    const int wid = tid >> 5, lane = tid & 31;
    const float* __restrict__ Whh = dir ? Whhb : Whhf;
    const float* __restrict__ xp = g_xp[dir];

    {
        const int n = tid >> 1;
        const int kh = (tid & 1) * 128;
        const int gr = (n >> 5)*HHX + jc*32 + (n & 31);
        const float* wrow = Whh + (size_t)gr*HHX + kh;
#pragma unroll 8
        for (int kk = 0; kk < 128; kk += 4) {
            float4 v = *(const float4*)&wrow[kk];
            __nv_bfloat16 h0,l0,h1,l1,h2,l2,h3,l3;
            bsplit(v.x,h0,l0); bsplit(v.y,h1,l1);
            bsplit(v.z,h2,l2); bsplit(v.w,h3,l3);
            uint32_t o = offB(n, kh + kk);
            *(__nv_bfloat162*)(sm + SMB_H + o)     = __halves2bfloat162(h0,h1);
            *(__nv_bfloat162*)(sm + SMB_H + o + 4) = __halves2bfloat162(h2,h3);
            *(__nv_bfloat162*)(sm + SMB_L + o)     = __halves2bfloat162(l0,l1);
            *(__nv_bfloat162*)(sm + SMB_L + o + 4) = __halves2bfloat162(l2,l3);
        }
    }
    {
        const int jj = tid & 31, r0 = (tid >> 5) * 8;
#pragma unroll
        for (int rr = 0; rr < 8; rr++)
            g_hbc[0][dir][rh*64 + r0 + rr][jc*32 + jj] = 0.f;
    }
    float cst[8];
#pragma unroll
    for (int i = 0; i < 8; i++) cst[i] = 0.f;
    __syncthreads();

    const int wm = (wid >> 1) * 16;
    const int wn = (wid & 1) * 64;
    const int gq8 = lane >> 3, lr = lane & 7;
    const int arow = wm + lr + ((gq8 & 1) << 3);
    const int ake  = (gq8 >> 1) << 3;
    const int brow = lr + ((gq8 >> 1) << 3);
    const int bke  = (gq8 & 1) << 3;

    int bs = 0, p = 0;
    {
        bs++;
        __threadfence();
        __syncthreads();
        if (tid == 0) {
            int old = atomicAdd(&g_bcnt, 1);
            if (old == 31) { atomicExch(&g_bcnt, 0); __threadfence(); atomicExch(&g_bsense, bs); }
            else { while (atomicAdd(&g_bsense, 0) != bs) ; }
        }
        __syncthreads();
    }

    for (int t = 0; t < LX; t++) {
        const int tseq = dir ? (LX - 1 - t) : t;
        float acc[8][4];
        {
            const int rl0 = wm + (lane >> 2);
            const size_t nib0 = ((size_t)(rh*64 + rl0)*LX + tseq) * 1024;
            const size_t nib1 = nib0 + (size_t)8*LX*1024;
#pragma unroll
            for (int nt = 0; nt < 8; nt++) {
                int n0 = wn + nt*8 + 2*(lane & 3);
                int gcol = (n0 >> 5)*HHX + jc*32 + (n0 & 31);
                float2 v0 = *(const float2*)&xp[nib0 + gcol];
                float2 v1 = *(const float2*)&xp[nib1 + gcol];
                acc[nt][0] = v0.x; acc[nt][1] = v0.y;
                acc[nt][2] = v1.x; acc[nt][3] = v1.y;
            }
        }
        {
            const int rl = tid >> 2;
            const int q0 = (tid & 3) * 16;
            const float* hrow = &g_hbc[p][dir][rh*64 + rl][0];
#pragma unroll 4
            for (int i = 0; i < 16; i++) {
                int c = (q0 + i) * 4;
                float4 v = *(const float4*)&hrow[c];
                __nv_bfloat16 h0,l0,h1,l1,h2,l2,h3,l3;
                bsplit(v.x,h0,l0); bsplit(v.y,h1,l1);
                bsplit(v.z,h2,l2); bsplit(v.w,h3,l3);
                uint32_t o = offA(rl, c);
                *(__nv_bfloat162*)(sm + SMA_H + o)     = __halves2bfloat162(h0,h1);
                *(__nv_bfloat162*)(sm + SMA_H + o + 4) = __halves2bfloat162(h2,h3);
                *(__nv_bfloat162*)(sm + SMA_L + o)     = __halves2bfloat162(l0,l1);
                *(__nv_bfloat162*)(sm + SMA_L + o + 4) = __halves2bfloat162(l2,l3);
            }
        }
        __syncthreads();
#pragma unroll 4
        for (int k0 = 0; k0 < 256; k0 += 16) {
            uint32_t ah[4], al[4];
            uint32_t oa = offA(arow, k0 + ake);
            ldsm4(ah, sb + SMA_H + oa);
            ldsm4(al, sb + SMA_L + oa);
            uint32_t bh[4][4], bl[4][4];
#pragma unroll
            for (int gg = 0; gg < 4; gg++) {
                uint32_t ob = offB(wn + gg*16 + brow, k0 + bke);
                ldsm4(bh[gg], sb + SMB_H + ob);
                ldsm4(bl[gg], sb + SMB_L + ob);
            }
#pragma unroll
            for (int nt = 0; nt < 8; nt++) {
                const uint32_t* bhp = &bh[nt >> 1][(nt & 1) * 2];
                const uint32_t* blp = &bl[nt >> 1][(nt & 1) * 2];
                mma16816(acc[nt], ah, bhp);
                mma16816(acc[nt], ah, blp);
                mma16816(acc[nt], al, bhp);
            }
        }
        {
            float* gbuf = (float*)(sm + SMGT);
            const int r0 = wm + (lane >> 2);
#pragma unroll
            for (int nt = 0; nt < 8; nt++) {
                int cc = wn + nt*8 + 2*(lane & 3);
                *(float2*)&gbuf[(size_t)r0*128 + cc]     = make_float2(acc[nt][0], acc[nt][1]);
                *(float2*)&gbuf[(size_t)(r0+8)*128 + cc] = make_float2(acc[nt][2], acc[nt][3]);
            }
        }
        __syncthreads();
        {
            const float* gbuf = (const float*)(sm + SMGT);
            const int jj = tid & 31, r0 = (tid >> 5) * 8;
#pragma unroll
            for (int rr = 0; rr < 8; rr++) {
                const int row = r0 + rr;
                float gi = gbuf[(size_t)row*128 + jj];
                float gf = gbuf[(size_t)row*128 + 32 + jj];
                float gg = gbuf[(size_t)row*128 + 64 + jj];
                float go = gbuf[(size_t)row*128 + 96 + jj];
                float si = fsig(gi), sf = fsig(gf), so = fsig(go);
                float tg = ftanh(gg);
                cst[rr] = sf*cst[rr] + si*tg;
                float hv = so * ftanh(cst[rr]);
                const int seqr = rh*64 + row;
                const size_t nidx = (size_t)seqr*LX + tseq;
                g_nrep[nidx*HX + (size_t)dir*HHX + jc*32 + jj] = hv;
                g_hbc[p ^ 1][dir][seqr][jc*32 + jj] = hv;
            }
        }
        bs++;
        __threadfence();
        __syncthreads();
        if (tid == 0) {
            int old = atomicAdd(&g_bcnt, 1);
            if (old == 31) { atomicExch(&g_bcnt, 0); __threadfence(); atomicExch(&g_bsense, bs); }
            else { while (atomicAdd(&g_bsense, 0) != bs) ; }
        }
        __syncthreads();
        p ^= 1;
    }
}

// ---------------- padding row + zero row N of hidden buffers ----------------
__global__ void k_pad_zero(const float* __restrict__ pad)
{
    int j = threadIdx.x;
    if (j < HX) {
        g_nrep[(size_t)NX*HX + j] = pad[j];
        g_hid[0][0][(size_t)NX*HX + j] = 0.f;
        g_hid[0][1][(size_t)NX*HX + j] = 0.f;
        g_hid[1][0][(size_t)NX*HX + j] = 0.f;
        g_hid[1][1][(size_t)NX*HX + j] = 0.f;
    }
}

// ------- gather + mean + concat -> bf16 hi/lo cat; optional len compute ----
// selfInd: self row = selfT[nodes[n]] (layer 0, nrep source, shared by dirs)
__global__ __launch_bounds__(128) void k_gm(
    const float* __restrict__ selfT, size_t sSelf,
    const float* __restrict__ neighT, size_t sNeigh,
    const int* __restrict__ nodes,
    const int* __restrict__ adjF, const int* __restrict__ adjB,
    int computeLen, int selfInd)
{
    const int n = blockIdx.x;
    const int dir = blockIdx.y;
    selfT  += (size_t)dir*sSelf;
    neighT += (size_t)dir*sNeigh;
    const int* adj = dir ? adjB : adjF;
    __nv_bfloat16* cath = g_cath[dir];
    __nv_bfloat16* catl = g_catl[dir];

    const int t = threadIdx.x;
    __shared__ int nb[SX];
    __shared__ float s_red[4][SX];
    __shared__ float s_inv;
    if (t < SX) nb[t] = adj[(size_t)nodes[n]*SX + t];
    if (!computeLen && t == 0) s_inv = 1.f / g_len[dir][n];
    __syncthreads();

    const int c = t * 4;
    float4 s = {0.f, 0.f, 0.f, 0.f};
    float rq[SX];
#pragma unroll
    for (int q = 0; q < SX; q++) {
        const float4 v = *(const float4*)&neighT[(size_t)nb[q]*HX + c];
        s.x += v.x; s.y += v.y; s.z += v.z; s.w += v.w;
        if (computeLen) {
            rq[q] = fmaxf(v.x, 0.f) + fmaxf(v.y, 0.f)
                  + fmaxf(v.z, 0.f) + fmaxf(v.w, 0.f);
        }
    }
    if (computeLen) {
        const int lane = t & 31, w = t >> 5;
#pragma unroll
        for (int q = 0; q < SX; q++) {
            float x = rq[q];
#pragma unroll
            for (int o = 16; o; o >>= 1) x += __shfl_xor_sync(0xffffffffu, x, o);
            if (lane == 0) s_red[w][q] = x;
        }
        __syncthreads();
        if (t == 0) {
            float cnt = 0.f;
#pragma unroll
            for (int q = 0; q < SX; q++) {
                float tot = s_red[0][q] + s_red[1][q] + s_red[2][q] + s_red[3][q];
                if (tot > 0.f) cnt += 1.f;
            }
            g_len[dir][n] = cnt;
            s_inv = 1.f / cnt;
        }
        __syncthreads();
    }
    const float invlen = s_inv;

    const size_t srow = selfInd ? (size_t)nodes[n] : (size_t)n;
    float4 sv = *(const float4*)&selfT[srow*HX + c];
    float4 m = {s.x*invlen, s.y*invlen, s.z*invlen, s.w*invlen};

    size_t o = (size_t)n*K_SAGE + c;
    __nv_bfloat16 h0,l0,h1,l1,h2,l2,h3,l3;
    bsplit(sv.x,h0,l0); bsplit(sv.y,h1,l1); bsplit(sv.z,h2,l2); bsplit(sv.w,h3,l3);
    *(__nv_bfloat162*)&cath[o]   = __halves2bfloat162(h0,h1);
    *(__nv_bfloat162*)&cath[o+2] = __halves2bfloat162(h2,h3);
    *(__nv_bfloat162*)&catl[o]   = __halves2bfloat162(l0,l1);
    *(__nv_bfloat162*)&catl[o+2] = __halves2bfloat162(l2,l3);

    bsplit(m.x,h0,l0); bsplit(m.y,h1,l1); bsplit(m.z,h2,l2); bsplit(m.w,h3,l3);
    *(__nv_bfloat162*)&cath[o+HX]   = __halves2bfloat162(h0,h1);
    *(__nv_bfloat162*)&cath[o+HX+2] = __halves2bfloat162(h2,h3);
    *(__nv_bfloat162*)&catl[o+HX]   = __halves2bfloat162(l0,l1);
    *(__nv_bfloat162*)&catl[o+HX+2] = __halves2bfloat162(l2,l3);
}

// ---------------- fused finalize + maxpool ----------------
__global__ __launch_bounds__(1024) void k_finpool(float* __restrict__ out, int fin)
{
    const int b = blockIdx.x;
    const int t = threadIdx.x;        // 0..1023
    const int dirv = t >> 9, cc = t & 511;
    const float* hsrc = g_hid[dirv][fin];
    float m = -3.402823466e38f;
    for (int l = 0; l < LX; l++) {
        const int n = b*LX + l;
        float v = hsrc[(size_t)n*HX + cc];
        out[(size_t)n*1024 + t] = v;
        m = fmaxf(m, v);
        if (t < 512)
            out[(size_t)OFF_OV + (size_t)n*HX + t] = g_nrep[(size_t)n*HX + t];
    }
    out[(size_t)OFF_GE + (size_t)b*1024 + t] = m;
}

// ============================ host launcher ================================
extern "C" void kernel_launch(void* const* d_in, const int* in_sizes, int n_in,
                              void* d_out, int out_size)
{
    const int*   feature_info = (const int*)d_in[0];
    const int*   batch_nodes  = (const int*)d_in[1];
    const int*   fw_adj       = (const int*)d_in[2];
    const int*   bw_adj       = (const int*)d_in[3];
    const float* W_emb        = (const float*)d_in[4];
    const float* Wih_f        = (const float*)d_in[5];
    const float* Whh_f        = (const float*)d_in[6];
    const float* bih_f        = (const float*)d_in[7];
    const float* bhh_f        = (const float*)d_in[8];
    const float* Wih_b        = (const float*)d_in[9];
    const float* Whh_b        = (const float*)d_in[10];
    const float* bih_b        = (const float*)d_in[11];
    const float* bhh_b        = (const float*)d_in[12];
    const float* padding_vec  = (const float*)d_in[13];
    const float* fw_W         = (const float*)d_in[14];
    const float* fw_b         = (const float*)d_in[15];
    const float* bw_W         = (const float*)d_in[16];
    const float* bw_b         = (const float*)d_in[17];
    float* out = (float*)d_out;

    const int DSMEM = 3*65536 + 1024;
    cudaFuncSetAttribute(k_mma_gemm, cudaFuncAttributeMaxDynamicSharedMemorySize, DSMEM);
    cudaFuncSetAttribute(k_lstm, cudaFuncAttributeMaxDynamicSharedMemorySize, LSTM_SMEM);

    float *p_nrep, *p_hid, *p_bias, *p_sbias, *p_xp;
    __nv_bfloat16 *p_embh, *p_embl, *p_wihh, *p_wihl, *p_wh, *p_wl, *p_cath, *p_catl;
    cudaGetSymbolAddress((void**)&p_nrep, g_nrep);
    cudaGetSymbolAddress((void**)&p_hid,  g_hid);
    cudaGetSymbolAddress((void**)&p_bias, g_bias);
    cudaGetSymbolAddress((void**)&p_sbias,g_sbias);
    cudaGetSymbolAddress((void**)&p_xp,   g_xp);
    cudaGetSymbolAddress((void**)&p_embh, g_embh);
    cudaGetSymbolAddress((void**)&p_embl, g_embl);
    cudaGetSymbolAddress((void**)&p_wihh, g_wihh);
    cudaGetSymbolAddress((void**)&p_wihl, g_wihl);
    cudaGetSymbolAddress((void**)&p_wh,   g_wh);
    cudaGetSymbolAddress((void**)&p_wl,   g_wl);
    cudaGetSymbolAddress((void**)&p_cath, g_cath);
    cudaGetSymbolAddress((void**)&p_catl, g_catl);

    const size_t HIDQ = (size_t)(NX+1)*HX;
    const size_t HIDD = 2*HIDQ;
    float* hid_d[2][2];
    for (int d = 0; d < 2; d++)
        for (int q = 0; q < 2; q++)
            hid_d[d][q] = p_hid + ((size_t)d*2 + q)*HIDQ;

    // 1. embed + weight preprocessing (SAGE split folded into LSTM launch)
    k_embed<<<(NX*EMBP + 255)/256, 256>>>(feature_info, W_emb);
    k_bias<<<(LAYERSX*HX + 255)/256, 256>>>(bih_f, bhh_f, bih_b, bhh_b, fw_b, bw_b);
    k_split_wih<<<(2*1024*EMBP + 255)/256, 256>>>(Wih_f, Wih_b);

    // 2. input projections, both dirs in one launch (bf16x3 mma)
    dim3 gxp(1024/128, NX/128, 2);
    k_mma_gemm<<<gxp, 256, DSMEM>>>(p_embh, p_embl, p_wihh, p_wihl,
                                    p_bias, p_xp, 1024, EMBP, 0,
                                    0, (size_t)1024*EMBP, 1024, (size_t)NX*1024);

    // 3. tensor-core persistent BiLSTM + concurrent SAGE weight split
    k_lstm<<<32 + NB_SPLIT, 256, LSTM_SMEM>>>(Whh_f, Whh_b, fw_W, bw_W);

    // 4. padding row / zero rows (init_hid eliminated via indirect self)
    k_pad_zero<<<1, 512>>>(padding_vec);

    // 5. 7 SAGE layers; layer 0 reads self directly from nrep[nodes[n]]
    int pin = 0;
    dim3 ggm(NX, 2);
    dim3 gsage(HX/128, NX/128, 2);
    for (int l = 0; l < LAYERSX; l++) {
        if (l == 0)
            k_gm<<<ggm, 128>>>(p_nrep, 0, p_nrep, 0,
                               batch_nodes, fw_adj, bw_adj, 1, 1);
        else
            k_gm<<<ggm, 128>>>(hid_d[0][pin], HIDD, hid_d[0][pin], HIDD,
                               batch_nodes, fw_adj, bw_adj, 0, 0);
        k_mma_gemm<<<gsage, 256, DSMEM>>>(
            p_cath, p_catl,
            p_wh + (size_t)l*HX*K_SAGE, p_wl + (size_t)l*HX*K_SAGE,
            p_sbias + (size_t)l*HX, hid_d[0][1 - pin],
            HX, K_SAGE, 1,
            (size_t)NX*K_SAGE, (size_t)LAYERSX*HX*K_SAGE,
            (size_t)LAYERSX*HX, HIDD);
        pin ^= 1;
    }

    // 6. fused finalize + pool (final hidden in buffer index pin = 1)
    k_finpool<<<BX, 1024>>>(out, pin);
    (void)in_sizes; (void)n_in; (void)out_size;
}